// round 9
// baseline (speedup 1.0000x reference)
#include <cuda_runtime.h>
#include <cuda_bf16.h>
#include <cstdint>

#define N_NODES 100000
#define N_EDGES 1600000

__device__ float g_P[N_NODES * 64];
__device__ float g_Q[N_NODES * 64];

// Does this compilation pass have sm_10x 'a'-level features (tcgen05)?
#if defined(__CUDA_ARCH_FEAT_SM103_ALL) || defined(__CUDA_ARCH_FEAT_SM100_ALL) || defined(__CUDA_ARCH_FEAT_SM101_ALL)
#define HAS_TCGEN05 1
#else
#define HAS_TCGEN05 0
#endif

// ---------------- tensor-path smem layout ----------------
#define A_HI_OFF   0
#define A_LO_OFF   32768
#define BW1_HI_OFF 65536
#define BW1_LO_OFF 73728
#define BW2_HI_OFF 81920
#define BW2_LO_OFF 90112
#define TMEMP_OFF  98304
#define MBAR_OFF   98312
#define SB1_OFF    98368
#define SB2_OFF    98624
#define SG_OFF     98880
#define SBT_OFF    99136
#define SMEM_TOTAL 99840

// ---------------- scalar-fallback smem layout ----------------
#define F_H_OFF    0          // float[64*256]
#define F_W1C_OFF  65536      // float[32*64]
#define F_W2_OFF   73728      // float[64*64]
#define F_II_OFF   90112      // int[256]
#define F_IJ_OFF   91136      // int[256]
#define F_B_OFF    92160      // b1,b2,g,bt  float[64] each

#define IDESC 0x8100490u
#define SW(o) ((o) ^ (((o) >> 3) & 0x70))

static __device__ __forceinline__ uint32_t smem_u32(const void* p) {
    uint32_t a;
    asm("{ .reg .u64 t; cvta.to.shared.u64 t, %1; cvt.u32.u64 %0, t; }" : "=r"(a) : "l"(p));
    return a;
}
static __device__ __forceinline__ void red4(float* p, float a, float b, float c, float d) {
    asm volatile("red.global.add.v4.f32 [%0], {%1, %2, %3, %4};"
                 :: "l"(p), "f"(a), "f"(b), "f"(c), "f"(d) : "memory");
}
static __device__ __forceinline__ unsigned long long pack2(float a, float b) {
    unsigned long long r;
    asm("mov.b64 %0, {%1, %2};" : "=l"(r) : "f"(a), "f"(b));
    return r;
}
static __device__ __forceinline__ void unpack2(unsigned long long v, float& a, float& b) {
    asm("mov.b64 {%0, %1}, %2;" : "=f"(a), "=f"(b) : "l"(v));
}
static __device__ __forceinline__ unsigned long long ffma2(unsigned long long a,
                                                           unsigned long long b,
                                                           unsigned long long c) {
    unsigned long long d;
    asm("fma.rn.f32x2 %0, %1, %2, %3;" : "=l"(d) : "l"(a), "l"(b), "l"(c));
    return d;
}
static __device__ __forceinline__ unsigned long long fadd2(unsigned long long a,
                                                           unsigned long long b) {
    unsigned long long d;
    asm("add.rn.f32x2 %0, %1, %2;" : "=l"(d) : "l"(a), "l"(b));
    return d;
}
static __device__ __forceinline__ uint32_t pack_bf16(float f0, float f1) {
    __nv_bfloat16 h0 = __float2bfloat16(f0);
    __nv_bfloat16 h1 = __float2bfloat16(f1);
    return ((uint32_t)__bfloat16_as_ushort(h1) << 16) | (uint32_t)__bfloat16_as_ushort(h0);
}

#if HAS_TCGEN05
static __device__ __forceinline__ uint32_t elect_one() {
    uint32_t p;
    asm volatile("{\n\t.reg .pred p;\n\telect.sync _|p, 0xFFFFFFFF;\n\tselp.b32 %0, 1, 0, p;\n\t}" : "=r"(p));
    return p;
}
static __device__ __forceinline__ uint64_t mk_desc(uint32_t addr) {
    const uint64_t base = (2ULL << 61) | (1ULL << 46) | (64ULL << 32) | (1ULL << 16);
    return base | ((uint64_t)(addr >> 4) & 0x3FFF);
}
static __device__ __forceinline__ void mma_f16_ss(uint32_t d, uint64_t a, uint64_t b,
                                                  uint32_t idesc, int en) {
    asm volatile(
        "{\n\t.reg .pred p;\n\tsetp.ne.u32 p, %5, 0;\n\t"
        "tcgen05.mma.cta_group::1.kind::f16 [%0], %1, %2, %3, {%4, %4, %4, %4}, p;\n\t}"
        :: "r"(d), "l"(a), "l"(b), "r"(idesc), "r"(0u), "r"(en) : "memory");
}
#define TC_ALLOC(sl, n) asm volatile("tcgen05.alloc.cta_group::1.sync.aligned.shared::cta.b32 [%0], %1;" :: "r"(sl), "r"(n) : "memory")
#define TC_DEALLOC(tm, n) asm volatile("tcgen05.dealloc.cta_group::1.sync.aligned.b32 %0, %1;" :: "r"(tm), "r"(n))
#define TC_COMMIT(mb) asm volatile("tcgen05.commit.cta_group::1.mbarrier::arrive::one.shared::cluster.b64 [%0];" :: "r"(mb) : "memory")
#define TC_WAIT_LD() asm volatile("tcgen05.wait::ld.sync.aligned;" ::: "memory")
#define TC_FENCE_AFTER() asm volatile("tcgen05.fence::after_thread_sync;" ::: "memory")
#define FENCE_ASYNC() asm volatile("fence.proxy.async.shared::cta;" ::: "memory")
#define MBAR_INIT(mb, c) asm volatile("mbarrier.init.shared.b64 [%0], %1;" :: "r"(mb), "r"(c) : "memory")
#define MBAR_INVAL(mb) asm volatile("mbarrier.inval.shared.b64 [%0];" :: "r"(mb) : "memory")
#define MBAR_WAIT(mb, ph) do { \
    asm volatile( \
        "{\n\t.reg .pred P1;\n\t" \
        "WL_%=:\n\t" \
        "mbarrier.try_wait.parity.acquire.cta.shared::cta.b64 P1, [%0], %1, 0x989680;\n\t" \
        "@P1 bra.uni WD_%=;\n\t" \
        "bra.uni WL_%=;\n\t" \
        "WD_%=:\n\t}" :: "r"(mb), "r"(ph) : "memory"); \
} while (0)
#define LDTM32(r, a) \
    asm volatile("tcgen05.ld.sync.aligned.32x32b.x32.b32 " \
        "{%0, %1, %2, %3, %4, %5, %6, %7, %8, %9, %10, %11, %12, %13, %14, %15, " \
        " %16, %17, %18, %19, %20, %21, %22, %23, %24, %25, %26, %27, %28, %29, %30, %31}, [%32];" \
        : "=r"((r)[0]), "=r"((r)[1]), "=r"((r)[2]), "=r"((r)[3]), "=r"((r)[4]), "=r"((r)[5]), \
          "=r"((r)[6]), "=r"((r)[7]), "=r"((r)[8]), "=r"((r)[9]), "=r"((r)[10]), "=r"((r)[11]), \
          "=r"((r)[12]), "=r"((r)[13]), "=r"((r)[14]), "=r"((r)[15]), "=r"((r)[16]), "=r"((r)[17]), \
          "=r"((r)[18]), "=r"((r)[19]), "=r"((r)[20]), "=r"((r)[21]), "=r"((r)[22]), "=r"((r)[23]), \
          "=r"((r)[24]), "=r"((r)[25]), "=r"((r)[26]), "=r"((r)[27]), "=r"((r)[28]), "=r"((r)[29]), \
          "=r"((r)[30]), "=r"((r)[31]) : "r"(a))
#endif  // HAS_TCGEN05

__global__ void zero_kernel(float4* __restrict__ out) {
    out[blockIdx.x * 256 + threadIdx.x] = make_float4(0.f, 0.f, 0.f, 0.f);
}

__global__ void __launch_bounds__(128) pq_kernel(const float* __restrict__ x,
                                                 const float* __restrict__ W1) {
    const float* Wbase = W1 + (size_t)blockIdx.y * 64 * 64;
    float* dst = blockIdx.y ? g_Q : g_P;
    const int l = threadIdx.x & 31;
    const int warp = (blockIdx.x * 128 + threadIdx.x) >> 5;
    const int nwarps = gridDim.x * 4;

    unsigned long long w[64];
#pragma unroll
    for (int k = 0; k < 64; k++)
        w[k] = *(const unsigned long long*)(Wbase + k * 64 + 2 * l);

    for (int n = warp; n < N_NODES; n += nwarps) {
        const float4* xr = (const float4*)(x + (size_t)n * 64);
        unsigned long long aA = 0ULL, aB = 0ULL;
#pragma unroll
        for (int k4 = 0; k4 < 16; k4++) {
            float4 xv = __ldg(xr + k4);
            aA = ffma2(pack2(xv.x, xv.x), w[4 * k4 + 0], aA);
            aB = ffma2(pack2(xv.y, xv.y), w[4 * k4 + 1], aB);
            aA = ffma2(pack2(xv.z, xv.z), w[4 * k4 + 2], aA);
            aB = ffma2(pack2(xv.w, xv.w), w[4 * k4 + 3], aB);
        }
        *(unsigned long long*)(dst + (size_t)n * 64 + 2 * l) = fadd2(aA, aB);
    }
}

// ================== edge kernel: 256 edges/CTA, dual-path ==================
__global__ void __launch_bounds__(256, 2) edge_kernel(
    const int* __restrict__ eidx, const float* __restrict__ eattr,
    const float* __restrict__ W1, const float* __restrict__ b1,
    const float* __restrict__ gamma_, const float* __restrict__ beta_,
    const float* __restrict__ W2, const float* __restrict__ b2,
    float* __restrict__ out) {
    extern __shared__ __align__(1024) char smem[];
    const int t = threadIdx.x;
    const int Eb = blockIdx.x * 256;

#if HAS_TCGEN05
    // ======================= tcgen05 path =======================
    const uint32_t sbase = smem_u32(smem);
    const int wg = t >> 7;
    const int r = t & 127;

    float* sB1 = (float*)(smem + SB1_OFF);
    float* sB2 = (float*)(smem + SB2_OFF);
    float* sG = (float*)(smem + SG_OFF);
    float* sBt = (float*)(smem + SBT_OFF);
    const uint32_t mbar = sbase + MBAR_OFF;

    if (t < 32) TC_ALLOC(sbase + TMEMP_OFF, 128);

    for (int idx = t; idx < 2048; idx += 256) {
        int n = idx & 63, k = idx >> 6;
        float v = W1[(size_t)(128 + k) * 64 + n];
        __nv_bfloat16 hi = __float2bfloat16(v);
        __nv_bfloat16 lo = __float2bfloat16(v - __bfloat162float(hi));
        int so = SW(n * 128 + k * 2);
        *(__nv_bfloat16*)(smem + BW1_HI_OFF + so) = hi;
        *(__nv_bfloat16*)(smem + BW1_LO_OFF + so) = lo;
    }
    for (int idx = t; idx < 4096; idx += 256) {
        int n = idx & 63, k = idx >> 6;
        float v = W2[(size_t)k * 64 + n];
        __nv_bfloat16 hi = __float2bfloat16(v);
        __nv_bfloat16 lo = __float2bfloat16(v - __bfloat162float(hi));
        int so = SW(n * 128 + k * 2);
        *(__nv_bfloat16*)(smem + BW2_HI_OFF + so) = hi;
        *(__nv_bfloat16*)(smem + BW2_LO_OFF + so) = lo;
    }
    if (t < 64) { sB1[t] = b1[t]; sB2[t] = b2[t]; sG[t] = gamma_[t]; sBt[t] = beta_[t]; }
    if (t == 0) MBAR_INIT(mbar, 1);

    const int vi = eidx[Eb + t];
    const int vj = eidx[N_EDGES + Eb + t];
    {
        const float4* ef = (const float4*)(eattr + (size_t)(Eb + t) * 32);
        float ev[32];
#pragma unroll
        for (int i = 0; i < 8; i++) {
            float4 v = __ldg(ef + i);
            ev[4 * i] = v.x; ev[4 * i + 1] = v.y; ev[4 * i + 2] = v.z; ev[4 * i + 3] = v.w;
        }
        char* aHi = smem + A_HI_OFF + wg * 16384;
        char* aLo = smem + A_LO_OFF + wg * 16384;
#pragma unroll
        for (int c = 0; c < 4; c++) {
            uint32_t hw[4], lw[4];
#pragma unroll
            for (int p = 0; p < 4; p++) {
                float f0 = ev[c * 8 + 2 * p], f1 = ev[c * 8 + 2 * p + 1];
                __nv_bfloat16 h0 = __float2bfloat16(f0), h1 = __float2bfloat16(f1);
                hw[p] = ((uint32_t)__bfloat16_as_ushort(h1) << 16) | __bfloat16_as_ushort(h0);
                lw[p] = pack_bf16(f0 - __bfloat162float(h0), f1 - __bfloat162float(h1));
            }
            int so = SW(r * 128 + c * 16);
            *(uint4*)(aHi + so) = make_uint4(hw[0], hw[1], hw[2], hw[3]);
            *(uint4*)(aLo + so) = make_uint4(lw[0], lw[1], lw[2], lw[3]);
        }
    }
    FENCE_ASYNC();
    __syncthreads();

    uint32_t tmem;
    asm volatile("ld.shared.b32 %0, [%1];" : "=r"(tmem) : "r"(sbase + TMEMP_OFF));

    if (t < 32 && elect_one()) {
        uint64_t bh = mk_desc(sbase + BW1_HI_OFF);
        uint64_t bl = mk_desc(sbase + BW1_LO_OFF);
#pragma unroll
        for (int tile = 0; tile < 2; tile++) {
            uint32_t dcol = tmem + tile * 64;
            uint64_t ah = mk_desc(sbase + A_HI_OFF + tile * 16384);
            uint64_t al = mk_desc(sbase + A_LO_OFF + tile * 16384);
            uint64_t ads[3] = {ah, al, ah};
            uint64_t bds[3] = {bh, bh, bl};
#pragma unroll
            for (int term = 0; term < 3; term++)
#pragma unroll
                for (int k = 0; k < 2; k++)
                    mma_f16_ss(dcol, ads[term] + k * 2, bds[term] + k * 2, IDESC,
                               (term | k) != 0);
        }
        TC_COMMIT(mbar);
    }
    MBAR_WAIT(mbar, 0);
    TC_FENCE_AFTER();

    const float* Pr = g_P + (size_t)vi * 64;
    const float* Qr = g_Q + (size_t)vj * 64;
    float h[64];
    {
        uint32_t d[32];
        LDTM32(d, tmem + wg * 64);
        TC_WAIT_LD();
#pragma unroll
        for (int c4 = 0; c4 < 8; c4++) {
            float4 p = __ldg((const float4*)Pr + c4);
            float4 q = __ldg((const float4*)Qr + c4);
            float4 bb = *(const float4*)(sB1 + 4 * c4);
            h[4 * c4 + 0] = __uint_as_float(d[4 * c4 + 0]) + p.x + q.x + bb.x;
            h[4 * c4 + 1] = __uint_as_float(d[4 * c4 + 1]) + p.y + q.y + bb.y;
            h[4 * c4 + 2] = __uint_as_float(d[4 * c4 + 2]) + p.z + q.z + bb.z;
            h[4 * c4 + 3] = __uint_as_float(d[4 * c4 + 3]) + p.w + q.w + bb.w;
        }
        LDTM32(d, tmem + wg * 64 + 32);
        TC_WAIT_LD();
#pragma unroll
        for (int c4 = 0; c4 < 8; c4++) {
            float4 p = __ldg((const float4*)Pr + 8 + c4);
            float4 q = __ldg((const float4*)Qr + 8 + c4);
            float4 bb = *(const float4*)(sB1 + 32 + 4 * c4);
            h[32 + 4 * c4 + 0] = __uint_as_float(d[4 * c4 + 0]) + p.x + q.x + bb.x;
            h[32 + 4 * c4 + 1] = __uint_as_float(d[4 * c4 + 1]) + p.y + q.y + bb.y;
            h[32 + 4 * c4 + 2] = __uint_as_float(d[4 * c4 + 2]) + p.z + q.z + bb.z;
            h[32 + 4 * c4 + 3] = __uint_as_float(d[4 * c4 + 3]) + p.w + q.w + bb.w;
        }
    }
    float s = 0.f, ss = 0.f;
#pragma unroll
    for (int c = 0; c < 64; c++) { s += h[c]; ss += h[c] * h[c]; }
    const float mu = s * (1.0f / 64.0f);
    const float var = ss * (1.0f / 64.0f) - mu * mu;
    const float rstd = rsqrtf(var + 1e-5f);
#pragma unroll
    for (int c = 0; c < 64; c++) {
        float v = (h[c] - mu) * rstd * sG[c] + sBt[c];
        h[c] = 0.5f * v * (1.0f + erff(v * 0.70710678118654752f));
    }
    {
        char* aHi = smem + A_HI_OFF + wg * 16384;
        char* aLo = smem + A_LO_OFF + wg * 16384;
#pragma unroll
        for (int c = 0; c < 8; c++) {
            uint32_t hw[4], lw[4];
#pragma unroll
            for (int p = 0; p < 4; p++) {
                float f0 = h[c * 8 + 2 * p], f1 = h[c * 8 + 2 * p + 1];
                __nv_bfloat16 h0 = __float2bfloat16(f0), h1 = __float2bfloat16(f1);
                hw[p] = ((uint32_t)__bfloat16_as_ushort(h1) << 16) | __bfloat16_as_ushort(h0);
                lw[p] = pack_bf16(f0 - __bfloat162float(h0), f1 - __bfloat162float(h1));
            }
            int so = SW(r * 128 + c * 16);
            *(uint4*)(aHi + so) = make_uint4(hw[0], hw[1], hw[2], hw[3]);
            *(uint4*)(aLo + so) = make_uint4(lw[0], lw[1], lw[2], lw[3]);
        }
    }
    FENCE_ASYNC();
    __syncthreads();

    if (t < 32 && elect_one()) {
        uint64_t bh = mk_desc(sbase + BW2_HI_OFF);
        uint64_t bl = mk_desc(sbase + BW2_LO_OFF);
#pragma unroll
        for (int tile = 0; tile < 2; tile++) {
            uint32_t dcol = tmem + tile * 64;
            uint64_t ah = mk_desc(sbase + A_HI_OFF + tile * 16384);
            uint64_t al = mk_desc(sbase + A_LO_OFF + tile * 16384);
            uint64_t ads[3] = {ah, al, ah};
            uint64_t bds[3] = {bh, bh, bl};
#pragma unroll
            for (int term = 0; term < 3; term++)
#pragma unroll
                for (int k = 0; k < 4; k++)
                    mma_f16_ss(dcol, ads[term] + k * 2, bds[term] + k * 2, IDESC,
                               (term | k) != 0);
        }
        TC_COMMIT(mbar);
    }
    MBAR_WAIT(mbar, 1);
    TC_FENCE_AFTER();

    {
        float* op = out + (size_t)vj * 64;
        uint32_t d[32];
        LDTM32(d, tmem + wg * 64);
        TC_WAIT_LD();
#pragma unroll
        for (int c4 = 0; c4 < 8; c4++) {
            float4 bb = *(const float4*)(sB2 + 4 * c4);
            red4(op + 4 * c4,
                 __uint_as_float(d[4 * c4 + 0]) + bb.x,
                 __uint_as_float(d[4 * c4 + 1]) + bb.y,
                 __uint_as_float(d[4 * c4 + 2]) + bb.z,
                 __uint_as_float(d[4 * c4 + 3]) + bb.w);
        }
        LDTM32(d, tmem + wg * 64 + 32);
        TC_WAIT_LD();
#pragma unroll
        for (int c4 = 0; c4 < 8; c4++) {
            float4 bb = *(const float4*)(sB2 + 32 + 4 * c4);
            red4(op + 32 + 4 * c4,
                 __uint_as_float(d[4 * c4 + 0]) + bb.x,
                 __uint_as_float(d[4 * c4 + 1]) + bb.y,
                 __uint_as_float(d[4 * c4 + 2]) + bb.z,
                 __uint_as_float(d[4 * c4 + 3]) + bb.w);
        }
    }

    __syncthreads();
    if (t == 0) MBAR_INVAL(mbar);
    __syncthreads();
    if (t < 32) TC_DEALLOC(tmem, 128);

#else
    // ======================= scalar fallback (R3) =======================
    float* sH = (float*)(smem + F_H_OFF);
    float* sW1c = (float*)(smem + F_W1C_OFF);
    float* sW2 = (float*)(smem + F_W2_OFF);
    int* sIi = (int*)(smem + F_II_OFF);
    int* sIj = (int*)(smem + F_IJ_OFF);
    float* sB1 = (float*)(smem + F_B_OFF);
    float* sB2 = sB1 + 64;
    float* sG = sB1 + 128;
    float* sBt = sB1 + 192;

    const int tr = t >> 3;
    const int tc = t & 7;

    sIi[t] = eidx[Eb + t];
    sIj[t] = eidx[N_EDGES + Eb + t];
    {
        const float4* w1s = (const float4*)(W1 + 128 * 64);
#pragma unroll
        for (int i = 0; i < 2; i++) ((float4*)sW1c)[t + 256 * i] = w1s[t + 256 * i];
        const float4* w2s = (const float4*)W2;
#pragma unroll
        for (int i = 0; i < 4; i++) ((float4*)sW2)[t + 256 * i] = w2s[t + 256 * i];
        if (t < 64) { sB1[t] = b1[t]; sB2[t] = b2[t]; sG[t] = gamma_[t]; sBt[t] = beta_[t]; }
    }
    {
        const float4* er = (const float4*)(eattr + (size_t)(Eb + t) * 32);
        float4 ev[8];
#pragma unroll
        for (int i = 0; i < 8; i++) ev[i] = __ldg(er + i);
        const float* evf = (const float*)ev;
        const int ecbase = t >> 3, off = t & 7;
#pragma unroll
        for (int k = 0; k < 32; k++)
            sH[k * 256 + ((ecbase ^ (k >> 3)) & 31) * 8 + off] = evf[k];
    }
    __syncthreads();

    unsigned long long acc[8][4];
    {
        float4 b1a = *(const float4*)(sB1 + tc * 8);
        float4 b1b = *(const float4*)(sB1 + tc * 8 + 4);
#pragma unroll
        for (int e = 0; e < 8; e++) {
            const int vi = sIi[tr * 8 + e];
            const int vj = sIj[tr * 8 + e];
            const float* Pr = g_P + (size_t)vi * 64 + tc * 8;
            const float* Qr = g_Q + (size_t)vj * 64 + tc * 8;
            float4 pa = *(const float4*)Pr;
            float4 pb = *(const float4*)(Pr + 4);
            float4 qa = *(const float4*)Qr;
            float4 qb = *(const float4*)(Qr + 4);
            acc[e][0] = pack2(pa.x + qa.x + b1a.x, pa.y + qa.y + b1a.y);
            acc[e][1] = pack2(pa.z + qa.z + b1a.z, pa.w + qa.w + b1a.w);
            acc[e][2] = pack2(pb.x + qb.x + b1b.x, pb.y + qb.y + b1b.y);
            acc[e][3] = pack2(pb.z + qb.z + b1b.z, pb.w + qb.w + b1b.w);
        }
    }
#pragma unroll
    for (int k = 0; k < 32; k++) {
        const float* arow = sH + k * 256 + ((tr ^ (k >> 3)) & 31) * 8;
        float4 a0 = *(const float4*)arow;
        float4 a1 = *(const float4*)(arow + 4);
        const ulonglong2 w0 = *(const ulonglong2*)(sW1c + k * 64 + tc * 8);
        const ulonglong2 w1 = *(const ulonglong2*)(sW1c + k * 64 + tc * 8 + 4);
        const float a[8] = {a0.x, a0.y, a0.z, a0.w, a1.x, a1.y, a1.z, a1.w};
#pragma unroll
        for (int e = 0; e < 8; e++) {
            unsigned long long ae = pack2(a[e], a[e]);
            acc[e][0] = ffma2(ae, w0.x, acc[e][0]);
            acc[e][1] = ffma2(ae, w0.y, acc[e][1]);
            acc[e][2] = ffma2(ae, w1.x, acc[e][2]);
            acc[e][3] = ffma2(ae, w1.y, acc[e][3]);
        }
    }

    float s[8], ss[8];
#pragma unroll
    for (int e = 0; e < 8; e++) {
        float h0, h1, h2, h3, h4, h5, h6, h7;
        unpack2(acc[e][0], h0, h1); unpack2(acc[e][1], h2, h3);
        unpack2(acc[e][2], h4, h5); unpack2(acc[e][3], h6, h7);
        s[e] = ((h0 + h1) + (h2 + h3)) + ((h4 + h5) + (h6 + h7));
        ss[e] = ((h0 * h0 + h1 * h1) + (h2 * h2 + h3 * h3)) +
                ((h4 * h4 + h5 * h5) + (h6 * h6 + h7 * h7));
    }
#pragma unroll
    for (int m = 1; m < 8; m <<= 1) {
#pragma unroll
        for (int e = 0; e < 8; e++) {
            s[e] += __shfl_xor_sync(0xffffffffu, s[e], m);
            ss[e] += __shfl_xor_sync(0xffffffffu, ss[e], m);
        }
    }

    float4 ga = *(const float4*)(sG + tc * 8);
    float4 gb = *(const float4*)(sG + tc * 8 + 4);
    float4 ba = *(const float4*)(sBt + tc * 8);
    float4 bb = *(const float4*)(sBt + tc * 8 + 4);
    const float gg[8] = {ga.x, ga.y, ga.z, ga.w, gb.x, gb.y, gb.z, gb.w};
    const float bt[8] = {ba.x, ba.y, ba.z, ba.w, bb.x, bb.y, bb.z, bb.w};

    __syncthreads();

#pragma unroll
    for (int e = 0; e < 8; e++) {
        const float mu = s[e] * (1.0f / 64.0f);
        const float var = ss[e] * (1.0f / 64.0f) - mu * mu;
        const float rstd = rsqrtf(var + 1e-5f);
        float h[8];
        unpack2(acc[e][0], h[0], h[1]); unpack2(acc[e][1], h[2], h[3]);
        unpack2(acc[e][2], h[4], h[5]); unpack2(acc[e][3], h[6], h[7]);
#pragma unroll
        for (int c = 0; c < 8; c++) {
            float v = (h[c] - mu) * rstd * gg[c] + bt[c];
            h[c] = 0.5f * v * (1.0f + erff(v * 0.70710678118654752f));
        }
#pragma unroll
        for (int c = 0; c < 8; c++)
            sH[(tc * 8 + c) * 256 + ((tr ^ tc) & 31) * 8 + e] = h[c];
    }
    __syncthreads();

    {
        float4 b2a = *(const float4*)(sB2 + tc * 8);
        float4 b2b = *(const float4*)(sB2 + tc * 8 + 4);
#pragma unroll
        for (int e = 0; e < 8; e++) {
            acc[e][0] = pack2(b2a.x, b2a.y);
            acc[e][1] = pack2(b2a.z, b2a.w);
            acc[e][2] = pack2(b2b.x, b2b.y);
            acc[e][3] = pack2(b2b.z, b2b.w);
        }
    }
#pragma unroll
    for (int k = 0; k < 64; k++) {
        const float* arow = sH + k * 256 + ((tr ^ (k >> 3)) & 31) * 8;
        float4 a0 = *(const float4*)arow;
        float4 a1 = *(const float4*)(arow + 4);
        const ulonglong2 w0 = *(const ulonglong2*)(sW2 + k * 64 + tc * 8);
        const ulonglong2 w1 = *(const ulonglong2*)(sW2 + k * 64 + tc * 8 + 4);
        const float a[8] = {a0.x, a0.y, a0.z, a0.w, a1.x, a1.y, a1.z, a1.w};
#pragma unroll
        for (int e = 0; e < 8; e++) {
            unsigned long long ae = pack2(a[e], a[e]);
            acc[e][0] = ffma2(ae, w0.x, acc[e][0]);
            acc[e][1] = ffma2(ae, w0.y, acc[e][1]);
            acc[e][2] = ffma2(ae, w1.x, acc[e][2]);
            acc[e][3] = ffma2(ae, w1.y, acc[e][3]);
        }
    }

#pragma unroll
    for (int e = 0; e < 8; e++) {
        const int vj = sIj[tr * 8 + e];
        float* op = out + (size_t)vj * 64 + tc * 8;
        float m0, m1, m2, m3, m4, m5, m6, m7;
        unpack2(acc[e][0], m0, m1); unpack2(acc[e][1], m2, m3);
        unpack2(acc[e][2], m4, m5); unpack2(acc[e][3], m6, m7);
        red4(op, m0, m1, m2, m3);
        red4(op + 4, m4, m5, m6, m7);
    }
#endif
}

extern "C" void kernel_launch(void* const* d_in, const int* in_sizes, int n_in,
                              void* d_out, int out_size) {
    const float* x = (const float*)d_in[0];
    const int* eidx = (const int*)d_in[1];
    const float* eattr = (const float*)d_in[2];
    const float* W1 = (const float*)d_in[3];
    const float* b1 = (const float*)d_in[4];
    const float* gamma_ = (const float*)d_in[5];
    const float* beta_ = (const float*)d_in[6];
    const float* W2 = (const float*)d_in[7];
    const float* b2 = (const float*)d_in[8];
    float* out = (float*)d_out;

    cudaFuncSetAttribute(edge_kernel, cudaFuncAttributeMaxDynamicSharedMemorySize, SMEM_TOTAL);

    zero_kernel<<<6250, 256>>>((float4*)out);
    pq_kernel<<<dim3(1024, 2), 128>>>(x, W1);
    edge_kernel<<<6250, 256, SMEM_TOTAL>>>(eidx, eattr, W1, b1, gamma_, beta_, W2, b2, out);
}

// round 11
// speedup vs baseline: 1.1265x; 1.1265x over previous
#include <cuda_runtime.h>
#include <cuda_bf16.h>
#include <cstdint>

#define N_NODES 100000
#define N_EDGES 1600000

__device__ float g_P[N_NODES * 64];
__device__ float g_Q[N_NODES * 64];
// Pre-split weight tiles (bf16 hi/lo, SW128-swizzled, 128B rows, ready for MMA B operand)
__device__ __align__(16) uint8_t g_W1hi[8192], g_W1lo[8192];
__device__ __align__(16) uint8_t g_W2hi[8192], g_W2lo[8192];

#if defined(__CUDA_ARCH_FEAT_SM103_ALL) || defined(__CUDA_ARCH_FEAT_SM100_ALL) || defined(__CUDA_ARCH_FEAT_SM101_ALL)
#define HAS_TCGEN05 1
#else
#define HAS_TCGEN05 0
#endif

// ---------------- tensor-path smem layout ----------------
#define A_HI_OFF   0
#define A_LO_OFF   32768
#define BW1_HI_OFF 65536
#define BW1_LO_OFF 73728
#define BW2_HI_OFF 81920
#define BW2_LO_OFF 90112
#define TMEMP_OFF  98304
#define MBAR_OFF   98312
#define SB1_OFF    98368
#define SB2_OFF    98624
#define SG_OFF     98880
#define SBT_OFF    99136
#define SMEM_TOTAL 99840

// ---------------- scalar-fallback smem layout ----------------
#define F_H_OFF    0
#define F_W1C_OFF  65536
#define F_W2_OFF   73728
#define F_II_OFF   90112
#define F_IJ_OFF   91136
#define F_B_OFF    92160

#define IDESC 0x8100490u
#define SW(o) ((o) ^ (((o) >> 3) & 0x70))

static __device__ __forceinline__ uint32_t smem_u32(const void* p) {
    uint32_t a;
    asm("{ .reg .u64 t; cvta.to.shared.u64 t, %1; cvt.u32.u64 %0, t; }" : "=r"(a) : "l"(p));
    return a;
}
static __device__ __forceinline__ void red4(float* p, float a, float b, float c, float d) {
    asm volatile("red.global.add.v4.f32 [%0], {%1, %2, %3, %4};"
                 :: "l"(p), "f"(a), "f"(b), "f"(c), "f"(d) : "memory");
}
static __device__ __forceinline__ unsigned long long pack2(float a, float b) {
    unsigned long long r;
    asm("mov.b64 %0, {%1, %2};" : "=l"(r) : "f"(a), "f"(b));
    return r;
}
static __device__ __forceinline__ void unpack2(unsigned long long v, float& a, float& b) {
    asm("mov.b64 {%0, %1}, %2;" : "=f"(a), "=f"(b) : "l"(v));
}
static __device__ __forceinline__ unsigned long long ffma2(unsigned long long a,
                                                           unsigned long long b,
                                                           unsigned long long c) {
    unsigned long long d;
    asm("fma.rn.f32x2 %0, %1, %2, %3;" : "=l"(d) : "l"(a), "l"(b), "l"(c));
    return d;
}
static __device__ __forceinline__ unsigned long long fadd2(unsigned long long a,
                                                           unsigned long long b) {
    unsigned long long d;
    asm("add.rn.f32x2 %0, %1, %2;" : "=l"(d) : "l"(a), "l"(b));
    return d;
}
static __device__ __forceinline__ uint32_t pack_bf16(float f0, float f1) {
    __nv_bfloat16 h0 = __float2bfloat16(f0);
    __nv_bfloat16 h1 = __float2bfloat16(f1);
    return ((uint32_t)__bfloat16_as_ushort(h1) << 16) | (uint32_t)__bfloat16_as_ushort(h0);
}

#if HAS_TCGEN05
static __device__ __forceinline__ uint32_t elect_one() {
    uint32_t p;
    asm volatile("{\n\t.reg .pred p;\n\telect.sync _|p, 0xFFFFFFFF;\n\tselp.b32 %0, 1, 0, p;\n\t}" : "=r"(p));
    return p;
}
static __device__ __forceinline__ uint64_t mk_desc(uint32_t addr) {
    const uint64_t base = (2ULL << 61) | (1ULL << 46) | (64ULL << 32) | (1ULL << 16);
    return base | ((uint64_t)(addr >> 4) & 0x3FFF);
}
static __device__ __forceinline__ void mma_f16_ss(uint32_t d, uint64_t a, uint64_t b,
                                                  uint32_t idesc, int en) {
    asm volatile(
        "{\n\t.reg .pred p;\n\tsetp.ne.u32 p, %5, 0;\n\t"
        "tcgen05.mma.cta_group::1.kind::f16 [%0], %1, %2, %3, {%4, %4, %4, %4}, p;\n\t}"
        :: "r"(d), "l"(a), "l"(b), "r"(idesc), "r"(0u), "r"(en) : "memory");
}
#define TC_ALLOC(sl, n) asm volatile("tcgen05.alloc.cta_group::1.sync.aligned.shared::cta.b32 [%0], %1;" :: "r"(sl), "r"(n) : "memory")
#define TC_DEALLOC(tm, n) asm volatile("tcgen05.dealloc.cta_group::1.sync.aligned.b32 %0, %1;" :: "r"(tm), "r"(n))
#define TC_COMMIT(mb) asm volatile("tcgen05.commit.cta_group::1.mbarrier::arrive::one.shared::cluster.b64 [%0];" :: "r"(mb) : "memory")
#define TC_WAIT_LD() asm volatile("tcgen05.wait::ld.sync.aligned;" ::: "memory")
#define TC_WAIT_ST() asm volatile("tcgen05.wait::st.sync.aligned;" ::: "memory")
#define TC_FENCE_BEFORE() asm volatile("tcgen05.fence::before_thread_sync;" ::: "memory")
#define TC_FENCE_AFTER() asm volatile("tcgen05.fence::after_thread_sync;" ::: "memory")
#define FENCE_ASYNC() asm volatile("fence.proxy.async.shared::cta;" ::: "memory")
#define MBAR_INIT(mb, c) asm volatile("mbarrier.init.shared.b64 [%0], %1;" :: "r"(mb), "r"(c) : "memory")
#define MBAR_INVAL(mb) asm volatile("mbarrier.inval.shared.b64 [%0];" :: "r"(mb) : "memory")
#define MBAR_WAIT(mb, ph) do { \
    asm volatile( \
        "{\n\t.reg .pred P1;\n\t" \
        "WL_%=:\n\t" \
        "mbarrier.try_wait.parity.acquire.cta.shared::cta.b64 P1, [%0], %1, 0x989680;\n\t" \
        "@P1 bra.uni WD_%=;\n\t" \
        "bra.uni WL_%=;\n\t" \
        "WD_%=:\n\t}" :: "r"(mb), "r"(ph) : "memory"); \
} while (0)
#define LDTM32(r, a) \
    asm volatile("tcgen05.ld.sync.aligned.32x32b.x32.b32 " \
        "{%0, %1, %2, %3, %4, %5, %6, %7, %8, %9, %10, %11, %12, %13, %14, %15, " \
        " %16, %17, %18, %19, %20, %21, %22, %23, %24, %25, %26, %27, %28, %29, %30, %31}, [%32];" \
        : "=r"((r)[0]), "=r"((r)[1]), "=r"((r)[2]), "=r"((r)[3]), "=r"((r)[4]), "=r"((r)[5]), \
          "=r"((r)[6]), "=r"((r)[7]), "=r"((r)[8]), "=r"((r)[9]), "=r"((r)[10]), "=r"((r)[11]), \
          "=r"((r)[12]), "=r"((r)[13]), "=r"((r)[14]), "=r"((r)[15]), "=r"((r)[16]), "=r"((r)[17]), \
          "=r"((r)[18]), "=r"((r)[19]), "=r"((r)[20]), "=r"((r)[21]), "=r"((r)[22]), "=r"((r)[23]), \
          "=r"((r)[24]), "=r"((r)[25]), "=r"((r)[26]), "=r"((r)[27]), "=r"((r)[28]), "=r"((r)[29]), \
          "=r"((r)[30]), "=r"((r)[31]) : "r"(a))
#define STTM32(a, r) \
    asm volatile("tcgen05.st.sync.aligned.32x32b.x32.b32 [%0], " \
        "{%1, %2, %3, %4, %5, %6, %7, %8, %9, %10, %11, %12, %13, %14, %15, %16, " \
        " %17, %18, %19, %20, %21, %22, %23, %24, %25, %26, %27, %28, %29, %30, %31, %32};" \
        :: "r"(a), \
           "r"((r)[0]), "r"((r)[1]), "r"((r)[2]), "r"((r)[3]), "r"((r)[4]), "r"((r)[5]), \
           "r"((r)[6]), "r"((r)[7]), "r"((r)[8]), "r"((r)[9]), "r"((r)[10]), "r"((r)[11]), \
           "r"((r)[12]), "r"((r)[13]), "r"((r)[14]), "r"((r)[15]), "r"((r)[16]), "r"((r)[17]), \
           "r"((r)[18]), "r"((r)[19]), "r"((r)[20]), "r"((r)[21]), "r"((r)[22]), "r"((r)[23]), \
           "r"((r)[24]), "r"((r)[25]), "r"((r)[26]), "r"((r)[27]), "r"((r)[28]), "r"((r)[29]), \
           "r"((r)[30]), "r"((r)[31]) : "memory")
#endif  // HAS_TCGEN05

__global__ void zero_kernel(float4* __restrict__ out) {
    out[blockIdx.x * 256 + threadIdx.x] = make_float4(0.f, 0.f, 0.f, 0.f);
}

// one-time weight split into swizzled bf16 hi/lo tiles (4096 threads)
__global__ void split_weights_kernel(const float* __restrict__ W1,
                                     const float* __restrict__ W2) {
    const int t = blockIdx.x * 256 + threadIdx.x;
    if (t < 2048) {
        int n = t & 63, k = t >> 6;  // k: 0..31
        float v = W1[(size_t)(128 + k) * 64 + n];
        __nv_bfloat16 hi = __float2bfloat16(v);
        __nv_bfloat16 lo = __float2bfloat16(v - __bfloat162float(hi));
        int so = SW(n * 128 + k * 2);
        *(__nv_bfloat16*)(g_W1hi + so) = hi;
        *(__nv_bfloat16*)(g_W1lo + so) = lo;
    }
    if (t < 4096) {
        int n = t & 63, k = t >> 6;  // k: 0..63
        float v = W2[(size_t)k * 64 + n];
        __nv_bfloat16 hi = __float2bfloat16(v);
        __nv_bfloat16 lo = __float2bfloat16(v - __bfloat162float(hi));
        int so = SW(n * 128 + k * 2);
        *(__nv_bfloat16*)(g_W2hi + so) = hi;
        *(__nv_bfloat16*)(g_W2lo + so) = lo;
    }
}

__global__ void __launch_bounds__(128) pq_kernel(const float* __restrict__ x,
                                                 const float* __restrict__ W1) {
    const float* Wbase = W1 + (size_t)blockIdx.y * 64 * 64;
    float* dst = blockIdx.y ? g_Q : g_P;
    const int l = threadIdx.x & 31;
    const int warp = (blockIdx.x * 128 + threadIdx.x) >> 5;
    const int nwarps = gridDim.x * 4;

    unsigned long long w[64];
#pragma unroll
    for (int k = 0; k < 64; k++)
        w[k] = *(const unsigned long long*)(Wbase + k * 64 + 2 * l);

    for (int n = warp; n < N_NODES; n += nwarps) {
        const float4* xr = (const float4*)(x + (size_t)n * 64);
        unsigned long long aA = 0ULL, aB = 0ULL;
#pragma unroll
        for (int k4 = 0; k4 < 16; k4++) {
            float4 xv = __ldg(xr + k4);
            aA = ffma2(pack2(xv.x, xv.x), w[4 * k4 + 0], aA);
            aB = ffma2(pack2(xv.y, xv.y), w[4 * k4 + 1], aB);
            aA = ffma2(pack2(xv.z, xv.z), w[4 * k4 + 2], aA);
            aB = ffma2(pack2(xv.w, xv.w), w[4 * k4 + 3], aB);
        }
        *(unsigned long long*)(dst + (size_t)n * 64 + 2 * l) = fadd2(aA, aB);
    }
}

// ================== edge kernel: 256 edges/CTA, dual-path ==================
__global__ void __launch_bounds__(256, 2) edge_kernel(
    const int* __restrict__ eidx, const float* __restrict__ eattr,
    const float* __restrict__ W1, const float* __restrict__ b1,
    const float* __restrict__ gamma_, const float* __restrict__ beta_,
    const float* __restrict__ W2, const float* __restrict__ b2,
    float* __restrict__ out) {
    extern __shared__ __align__(1024) char smem[];
    const int t = threadIdx.x;
    const int Eb = blockIdx.x * 256;

#if HAS_TCGEN05
    // ======================= tcgen05 path =======================
    const uint32_t sbase = smem_u32(smem);
    const int wg = t >> 7;
    const int r = t & 127;

    float* sB1 = (float*)(smem + SB1_OFF);
    float* sB2 = (float*)(smem + SB2_OFF);
    float* sG = (float*)(smem + SG_OFF);
    float* sBt = (float*)(smem + SBT_OFF);
    const uint32_t mbar = sbase + MBAR_OFF;

    if (t < 32) TC_ALLOC(sbase + TMEMP_OFF, 128);

    // copy pre-split weight tiles (4 x 8KB, coalesced)
    {
        const uint4* w1h = (const uint4*)g_W1hi;
        const uint4* w1l = (const uint4*)g_W1lo;
        const uint4* w2h = (const uint4*)g_W2hi;
        const uint4* w2l = (const uint4*)g_W2lo;
#pragma unroll
        for (int i = t; i < 512; i += 256) {
            ((uint4*)(smem + BW1_HI_OFF))[i] = __ldg(w1h + i);
            ((uint4*)(smem + BW1_LO_OFF))[i] = __ldg(w1l + i);
            ((uint4*)(smem + BW2_HI_OFF))[i] = __ldg(w2h + i);
            ((uint4*)(smem + BW2_LO_OFF))[i] = __ldg(w2l + i);
        }
    }
    if (t < 64) { sB1[t] = b1[t]; sB2[t] = b2[t]; sG[t] = gamma_[t]; sBt[t] = beta_[t]; }
    if (t == 0) MBAR_INIT(mbar, 1);

    const int vi = eidx[Eb + t];
    const int vj = eidx[N_EDGES + Eb + t];

    // stage eattr row (edge = Eb + t) as bf16 hi/lo, chunked (low reg pressure)
    {
        const float4* ef = (const float4*)(eattr + (size_t)(Eb + t) * 32);
        char* aHi = smem + A_HI_OFF + wg * 16384;
        char* aLo = smem + A_LO_OFF + wg * 16384;
#pragma unroll
        for (int c = 0; c < 4; c++) {
            float4 e0 = __ldg(ef + 2 * c);
            float4 e1 = __ldg(ef + 2 * c + 1);
            const float ev[8] = {e0.x, e0.y, e0.z, e0.w, e1.x, e1.y, e1.z, e1.w};
            uint32_t hw[4], lw[4];
#pragma unroll
            for (int p = 0; p < 4; p++) {
                float f0 = ev[2 * p], f1 = ev[2 * p + 1];
                __nv_bfloat16 h0 = __float2bfloat16(f0), h1 = __float2bfloat16(f1);
                hw[p] = ((uint32_t)__bfloat16_as_ushort(h1) << 16) | __bfloat16_as_ushort(h0);
                lw[p] = pack_bf16(f0 - __bfloat162float(h0), f1 - __bfloat162float(h1));
            }
            int so = SW(r * 128 + c * 16);
            *(uint4*)(aHi + so) = make_uint4(hw[0], hw[1], hw[2], hw[3]);
            *(uint4*)(aLo + so) = make_uint4(lw[0], lw[1], lw[2], lw[3]);
        }
    }
    FENCE_ASYNC();
    __syncthreads();

    uint32_t tmem;
    asm volatile("ld.shared.b32 %0, [%1];" : "=r"(tmem) : "r"(sbase + TMEMP_OFF));

    // ---- MMA1: D = eattr @ W1c (3-term bf16 split, K=32) ----
    if (t < 32 && elect_one()) {
        uint64_t bh = mk_desc(sbase + BW1_HI_OFF);
        uint64_t bl = mk_desc(sbase + BW1_LO_OFF);
#pragma unroll
        for (int tile = 0; tile < 2; tile++) {
            uint32_t dcol = tmem + tile * 64;
            uint64_t ah = mk_desc(sbase + A_HI_OFF + tile * 16384);
            uint64_t al = mk_desc(sbase + A_LO_OFF + tile * 16384);
            uint64_t ads[3] = {ah, al, ah};
            uint64_t bds[3] = {bh, bh, bl};
#pragma unroll
            for (int term = 0; term < 3; term++)
#pragma unroll
                for (int k = 0; k < 2; k++)
                    mma_f16_ss(dcol, ads[term] + k * 2, bds[term] + k * 2, IDESC,
                               (term | k) != 0);
        }
        TC_COMMIT(mbar);
    }
    MBAR_WAIT(mbar, 0);
    TC_FENCE_AFTER();

    // ---- epilogue 1, pass 1: h = D + P + Q + b1 ; LN stats ; h back into TMEM ----
    const float* Pr = g_P + (size_t)vi * 64;
    const float* Qr = g_Q + (size_t)vj * 64;
    float s = 0.f, ss = 0.f;
#pragma unroll
    for (int half = 0; half < 2; half++) {
        uint32_t d[32];
        LDTM32(d, tmem + wg * 64 + half * 32);
        TC_WAIT_LD();
#pragma unroll
        for (int c4 = 0; c4 < 8; c4++) {
            float4 p = __ldg((const float4*)Pr + half * 8 + c4);
            float4 q = __ldg((const float4*)Qr + half * 8 + c4);
            float4 bb = *(const float4*)(sB1 + half * 32 + 4 * c4);
            float v0 = __uint_as_float(d[4 * c4 + 0]) + p.x + q.x + bb.x;
            float v1 = __uint_as_float(d[4 * c4 + 1]) + p.y + q.y + bb.y;
            float v2 = __uint_as_float(d[4 * c4 + 2]) + p.z + q.z + bb.z;
            float v3 = __uint_as_float(d[4 * c4 + 3]) + p.w + q.w + bb.w;
            s += (v0 + v1) + (v2 + v3);
            ss += (v0 * v0 + v1 * v1) + (v2 * v2 + v3 * v3);
            d[4 * c4 + 0] = __float_as_uint(v0);
            d[4 * c4 + 1] = __float_as_uint(v1);
            d[4 * c4 + 2] = __float_as_uint(v2);
            d[4 * c4 + 3] = __float_as_uint(v3);
        }
        STTM32(tmem + wg * 64 + half * 32, d);
    }
    TC_WAIT_ST();

    const float mu = s * (1.0f / 64.0f);
    const float var = ss * (1.0f / 64.0f) - mu * mu;
    const float rstd = rsqrtf(var + 1e-5f);

    // ---- epilogue 1, pass 2: reload h, normalize+GELU, split into A2 tiles ----
    {
        char* aHi = smem + A_HI_OFF + wg * 16384;  // alias: eattr tiles are dead (MMA1 done)
        char* aLo = smem + A_LO_OFF + wg * 16384;
#pragma unroll
        for (int half = 0; half < 2; half++) {
            uint32_t d[32];
            LDTM32(d, tmem + wg * 64 + half * 32);
            TC_WAIT_LD();
#pragma unroll
            for (int c = 0; c < 4; c++) {
                uint32_t hw[4], lw[4];
#pragma unroll
                for (int p = 0; p < 4; p++) {
                    int j = c * 8 + 2 * p;
                    int ch = half * 32 + j;
                    float u0 = (__uint_as_float(d[j]) - mu) * rstd * sG[ch] + sBt[ch];
                    float u1 = (__uint_as_float(d[j + 1]) - mu) * rstd * sG[ch + 1] + sBt[ch + 1];
                    float f0 = 0.5f * u0 * (1.0f + erff(u0 * 0.70710678118654752f));
                    float f1 = 0.5f * u1 * (1.0f + erff(u1 * 0.70710678118654752f));
                    __nv_bfloat16 h0 = __float2bfloat16(f0), h1 = __float2bfloat16(f1);
                    hw[p] = ((uint32_t)__bfloat16_as_ushort(h1) << 16) | __bfloat16_as_ushort(h0);
                    lw[p] = pack_bf16(f0 - __bfloat162float(h0), f1 - __bfloat162float(h1));
                }
                int so = SW(r * 128 + half * 64 + c * 16);
                *(uint4*)(aHi + so) = make_uint4(hw[0], hw[1], hw[2], hw[3]);
                *(uint4*)(aLo + so) = make_uint4(lw[0], lw[1], lw[2], lw[3]);
            }
        }
    }
    TC_FENCE_BEFORE();
    FENCE_ASYNC();
    __syncthreads();

    // ---- MMA2: D = h @ W2 (3-term split, K=64; en=0 first overwrites) ----
    if (t < 32 && elect_one()) {
        uint64_t bh = mk_desc(sbase + BW2_HI_OFF);
        uint64_t bl = mk_desc(sbase + BW2_LO_OFF);
#pragma unroll
        for (int tile = 0; tile < 2; tile++) {
            uint32_t dcol = tmem + tile * 64;
            uint64_t ah = mk_desc(sbase + A_HI_OFF + tile * 16384);
            uint64_t al = mk_desc(sbase + A_LO_OFF + tile * 16384);
            uint64_t ads[3] = {ah, al, ah};
            uint64_t bds[3] = {bh, bh, bl};
#pragma unroll
            for (int term = 0; term < 3; term++)
#pragma unroll
                for (int k = 0; k < 4; k++)
                    mma_f16_ss(dcol, ads[term] + k * 2, bds[term] + k * 2, IDESC,
                               (term | k) != 0);
        }
        TC_COMMIT(mbar);
    }
    MBAR_WAIT(mbar, 1);
    TC_FENCE_AFTER();

    // ---- epilogue 2: read D, add b2, scatter-add onto node vj ----
    {
        float* op = out + (size_t)vj * 64;
#pragma unroll
        for (int half = 0; half < 2; half++) {
            uint32_t d[32];
            LDTM32(d, tmem + wg * 64 + half * 32);
            TC_WAIT_LD();
#pragma unroll
            for (int c4 = 0; c4 < 8; c4++) {
                float4 bb = *(const float4*)(sB2 + half * 32 + 4 * c4);
                red4(op + half * 32 + 4 * c4,
                     __uint_as_float(d[4 * c4 + 0]) + bb.x,
                     __uint_as_float(d[4 * c4 + 1]) + bb.y,
                     __uint_as_float(d[4 * c4 + 2]) + bb.z,
                     __uint_as_float(d[4 * c4 + 3]) + bb.w);
            }
        }
    }

    __syncthreads();
    if (t == 0) MBAR_INVAL(mbar);
    __syncthreads();
    if (t < 32) TC_DEALLOC(tmem, 128);

#else
    // ======================= scalar fallback (R3) =======================
    float* sH = (float*)(smem + F_H_OFF);
    float* sW1c = (float*)(smem + F_W1C_OFF);
    float* sW2 = (float*)(smem + F_W2_OFF);
    int* sIi = (int*)(smem + F_II_OFF);
    int* sIj = (int*)(smem + F_IJ_OFF);
    float* sB1 = (float*)(smem + F_B_OFF);
    float* sB2 = sB1 + 64;
    float* sG = sB1 + 128;
    float* sBt = sB1 + 192;

    const int tr = t >> 3;
    const int tc = t & 7;

    sIi[t] = eidx[Eb + t];
    sIj[t] = eidx[N_EDGES + Eb + t];
    {
        const float4* w1s = (const float4*)(W1 + 128 * 64);
#pragma unroll
        for (int i = 0; i < 2; i++) ((float4*)sW1c)[t + 256 * i] = w1s[t + 256 * i];
        const float4* w2s = (const float4*)W2;
#pragma unroll
        for (int i = 0; i < 4; i++) ((float4*)sW2)[t + 256 * i] = w2s[t + 256 * i];
        if (t < 64) { sB1[t] = b1[t]; sB2[t] = b2[t]; sG[t] = gamma_[t]; sBt[t] = beta_[t]; }
    }
    {
        const float4* er = (const float4*)(eattr + (size_t)(Eb + t) * 32);
        float4 ev[8];
#pragma unroll
        for (int i = 0; i < 8; i++) ev[i] = __ldg(er + i);
        const float* evf = (const float*)ev;
        const int ecbase = t >> 3, off = t & 7;
#pragma unroll
        for (int k = 0; k < 32; k++)
            sH[k * 256 + ((ecbase ^ (k >> 3)) & 31) * 8 + off] = evf[k];
    }
    __syncthreads();

    unsigned long long acc[8][4];
    {
        float4 b1a = *(const float4*)(sB1 + tc * 8);
        float4 b1b = *(const float4*)(sB1 + tc * 8 + 4);
#pragma unroll
        for (int e = 0; e < 8; e++) {
            const int vi = sIi[tr * 8 + e];
            const int vj = sIj[tr * 8 + e];
            const float* Pr = g_P + (size_t)vi * 64 + tc * 8;
            const float* Qr = g_Q + (size_t)vj * 64 + tc * 8;
            float4 pa = *(const float4*)Pr;
            float4 pb = *(const float4*)(Pr + 4);
            float4 qa = *(const float4*)Qr;
            float4 qb = *(const float4*)(Qr + 4);
            acc[e][0] = pack2(pa.x + qa.x + b1a.x, pa.y + qa.y + b1a.y);
            acc[e][1] = pack2(pa.z + qa.z + b1a.z, pa.w + qa.w + b1a.w);
            acc[e][2] = pack2(pb.x + qb.x + b1b.x, pb.y + qb.y + b1b.y);
            acc[e][3] = pack2(pb.z + qb.z + b1b.z, pb.w + qb.w + b1b.w);
        }
    }
#pragma unroll
    for (int k = 0; k < 32; k++) {
        const float* arow = sH + k * 256 + ((tr ^ (k >> 3)) & 31) * 8;
        float4 a0 = *(const float4*)arow;
        float4 a1 = *(const float4*)(arow + 4);
        const ulonglong2 w0 = *(const ulonglong2*)(sW1c + k * 64 + tc * 8);
        const ulonglong2 w1 = *(const ulonglong2*)(sW1c + k * 64 + tc * 8 + 4);
        const float a[8] = {a0.x, a0.y, a0.z, a0.w, a1.x, a1.y, a1.z, a1.w};
#pragma unroll
        for (int e = 0; e < 8; e++) {
            unsigned long long ae = pack2(a[e], a[e]);
            acc[e][0] = ffma2(ae, w0.x, acc[e][0]);
            acc[e][1] = ffma2(ae, w0.y, acc[e][1]);
            acc[e][2] = ffma2(ae, w1.x, acc[e][2]);
            acc[e][3] = ffma2(ae, w1.y, acc[e][3]);
        }
    }

    float s[8], ss[8];
#pragma unroll
    for (int e = 0; e < 8; e++) {
        float h0, h1, h2, h3, h4, h5, h6, h7;
        unpack2(acc[e][0], h0, h1); unpack2(acc[e][1], h2, h3);
        unpack2(acc[e][2], h4, h5); unpack2(acc[e][3], h6, h7);
        s[e] = ((h0 + h1) + (h2 + h3)) + ((h4 + h5) + (h6 + h7));
        ss[e] = ((h0 * h0 + h1 * h1) + (h2 * h2 + h3 * h3)) +
                ((h4 * h4 + h5 * h5) + (h6 * h6 + h7 * h7));
    }
#pragma unroll
    for (int m = 1; m < 8; m <<= 1) {
#pragma unroll
        for (int e = 0; e < 8; e++) {
            s[e] += __shfl_xor_sync(0xffffffffu, s[e], m);
            ss[e] += __shfl_xor_sync(0xffffffffu, ss[e], m);
        }
    }

    float4 ga = *(const float4*)(sG + tc * 8);
    float4 gb = *(const float4*)(sG + tc * 8 + 4);
    float4 ba = *(const float4*)(sBt + tc * 8);
    float4 bb = *(const float4*)(sBt + tc * 8 + 4);
    const float gg[8] = {ga.x, ga.y, ga.z, ga.w, gb.x, gb.y, gb.z, gb.w};
    const float bt[8] = {ba.x, ba.y, ba.z, ba.w, bb.x, bb.y, bb.z, bb.w};

    __syncthreads();

#pragma unroll
    for (int e = 0; e < 8; e++) {
        const float mu = s[e] * (1.0f / 64.0f);
        const float var = ss[e] * (1.0f / 64.0f) - mu * mu;
        const float rstd = rsqrtf(var + 1e-5f);
        float h[8];
        unpack2(acc[e][0], h[0], h[1]); unpack2(acc[e][1], h[2], h[3]);
        unpack2(acc[e][2], h[4], h[5]); unpack2(acc[e][3], h[6], h[7]);
#pragma unroll
        for (int c = 0; c < 8; c++) {
            float v = (h[c] - mu) * rstd * gg[c] + bt[c];
            h[c] = 0.5f * v * (1.0f + erff(v * 0.70710678118654752f));
        }
#pragma unroll
        for (int c = 0; c < 8; c++)
            sH[(tc * 8 + c) * 256 + ((tr ^ tc) & 31) * 8 + e] = h[c];
    }
    __syncthreads();

    {
        float4 b2a = *(const float4*)(sB2 + tc * 8);
        float4 b2b = *(const float4*)(sB2 + tc * 8 + 4);
#pragma unroll
        for (int e = 0; e < 8; e++) {
            acc[e][0] = pack2(b2a.x, b2a.y);
            acc[e][1] = pack2(b2a.z, b2a.w);
            acc[e][2] = pack2(b2b.x, b2b.y);
            acc[e][3] = pack2(b2b.z, b2b.w);
        }
    }
#pragma unroll
    for (int k = 0; k < 64; k++) {
        const float* arow = sH + k * 256 + ((tr ^ (k >> 3)) & 31) * 8;
        float4 a0 = *(const float4*)arow;
        float4 a1 = *(const float4*)(arow + 4);
        const ulonglong2 w0 = *(const ulonglong2*)(sW2 + k * 64 + tc * 8);
        const ulonglong2 w1 = *(const ulonglong2*)(sW2 + k * 64 + tc * 8 + 4);
        const float a[8] = {a0.x, a0.y, a0.z, a0.w, a1.x, a1.y, a1.z, a1.w};
#pragma unroll
        for (int e = 0; e < 8; e++) {
            unsigned long long ae = pack2(a[e], a[e]);
            acc[e][0] = ffma2(ae, w0.x, acc[e][0]);
            acc[e][1] = ffma2(ae, w0.y, acc[e][1]);
            acc[e][2] = ffma2(ae, w1.x, acc[e][2]);
            acc[e][3] = ffma2(ae, w1.y, acc[e][3]);
        }
    }

#pragma unroll
    for (int e = 0; e < 8; e++) {
        const int vj = sIj[tr * 8 + e];
        float* op = out + (size_t)vj * 64 + tc * 8;
        float m0, m1, m2, m3, m4, m5, m6, m7;
        unpack2(acc[e][0], m0, m1); unpack2(acc[e][1], m2, m3);
        unpack2(acc[e][2], m4, m5); unpack2(acc[e][3], m6, m7);
        red4(op, m0, m1, m2, m3);
        red4(op + 4, m4, m5, m6, m7);
    }
#endif
}

extern "C" void kernel_launch(void* const* d_in, const int* in_sizes, int n_in,
                              void* d_out, int out_size) {
    const float* x = (const float*)d_in[0];
    const int* eidx = (const int*)d_in[1];
    const float* eattr = (const float*)d_in[2];
    const float* W1 = (const float*)d_in[3];
    const float* b1 = (const float*)d_in[4];
    const float* gamma_ = (const float*)d_in[5];
    const float* beta_ = (const float*)d_in[6];
    const float* W2 = (const float*)d_in[7];
    const float* b2 = (const float*)d_in[8];
    float* out = (float*)d_out;

    cudaFuncSetAttribute(edge_kernel, cudaFuncAttributeMaxDynamicSharedMemorySize, SMEM_TOTAL);

    zero_kernel<<<6250, 256>>>((float4*)out);
    split_weights_kernel<<<16, 256>>>(W1, W2);
    pq_kernel<<<dim3(1024, 2), 128>>>(x, W1);
    edge_kernel<<<6250, 256, SMEM_TOTAL>>>(eidx, eattr, W1, b1, gamma_, beta_, W2, b2, out);
}

// round 14
// speedup vs baseline: 1.1916x; 1.0578x over previous
#include <cuda_runtime.h>
#include <cuda_bf16.h>
#include <cstdint>

#define N_NODES 100000
#define N_EDGES 1600000
#define N_TILES 6250
#define GRID_PERSIST 296

__device__ float g_P[N_NODES * 64];
__device__ float g_Q[N_NODES * 64];
__device__ __align__(16) uint8_t g_W1hi[8192], g_W1lo[8192];
__device__ __align__(16) uint8_t g_W2hi[8192], g_W2lo[8192];

#if defined(__CUDA_ARCH_FEAT_SM103_ALL) || defined(__CUDA_ARCH_FEAT_SM100_ALL) || defined(__CUDA_ARCH_FEAT_SM101_ALL)
#define HAS_TCGEN05 1
#else
#define HAS_TCGEN05 0
#endif

// ---------------- tensor-path smem layout ----------------
#define A_HI_OFF   0
#define A_LO_OFF   32768
#define BW1_HI_OFF 65536
#define BW1_LO_OFF 73728
#define BW2_HI_OFF 81920
#define BW2_LO_OFF 90112
#define TMEMP_OFF  98304
#define MBAR_OFF   98312
#define SB1_OFF    98368
#define SB2_OFF    98624
#define SG_OFF     98880
#define SBT_OFF    99136
#define SMEM_TOTAL 99840

// ---------------- scalar-fallback smem layout ----------------
#define F_H_OFF    0
#define F_W1C_OFF  65536
#define F_W2_OFF   73728
#define F_II_OFF   90112
#define F_IJ_OFF   91136
#define F_B_OFF    92160

#define IDESC 0x8100490u
#define SW(o) ((o) ^ (((o) >> 3) & 0x70))

static __device__ __forceinline__ uint32_t smem_u32(const void* p) {
    uint32_t a;
    asm("{ .reg .u64 t; cvta.to.shared.u64 t, %1; cvt.u32.u64 %0, t; }" : "=r"(a) : "l"(p));
    return a;
}
static __device__ __forceinline__ void red4(float* p, float a, float b, float c, float d) {
    asm volatile("red.global.add.v4.f32 [%0], {%1, %2, %3, %4};"
                 :: "l"(p), "f"(a), "f"(b), "f"(c), "f"(d) : "memory");
}
static __device__ __forceinline__ unsigned long long pack2(float a, float b) {
    unsigned long long r;
    asm("mov.b64 %0, {%1, %2};" : "=l"(r) : "f"(a), "f"(b));
    return r;
}
static __device__ __forceinline__ void unpack2(unsigned long long v, float& a, float& b) {
    asm("mov.b64 {%0, %1}, %2;" : "=f"(a), "=f"(b) : "l"(v));
}
static __device__ __forceinline__ unsigned long long ffma2(unsigned long long a,
                                                           unsigned long long b,
                                                           unsigned long long c) {
    unsigned long long d;
    asm("fma.rn.f32x2 %0, %1, %2, %3;" : "=l"(d) : "l"(a), "l"(b), "l"(c));
    return d;
}
static __device__ __forceinline__ unsigned long long fadd2(unsigned long long a,
                                                           unsigned long long b) {
    unsigned long long d;
    asm("add.rn.f32x2 %0, %1, %2;" : "=l"(d) : "l"(a), "l"(b));
    return d;
}
static __device__ __forceinline__ uint32_t pack_bf16(float f0, float f1) {
    __nv_bfloat16 h0 = __float2bfloat16(f0);
    __nv_bfloat16 h1 = __float2bfloat16(f1);
    return ((uint32_t)__bfloat16_as_ushort(h1) << 16) | (uint32_t)__bfloat16_as_ushort(h0);
}

#if HAS_TCGEN05
static __device__ __forceinline__ uint32_t elect_one() {
    uint32_t p;
    asm volatile("{\n\t.reg .pred p;\n\telect.sync _|p, 0xFFFFFFFF;\n\tselp.b32 %0, 1, 0, p;\n\t}" : "=r"(p));
    return p;
}
static __device__ __forceinline__ uint64_t mk_desc(uint32_t addr) {
    const uint64_t base = (2ULL << 61) | (1ULL << 46) | (64ULL << 32) | (1ULL << 16);
    return base | ((uint64_t)(addr >> 4) & 0x3FFF);
}
static __device__ __forceinline__ void mma_f16_ss(uint32_t d, uint64_t a, uint64_t b,
                                                  uint32_t idesc, int en) {
    asm volatile(
        "{\n\t.reg .pred p;\n\tsetp.ne.u32 p, %5, 0;\n\t"
        "tcgen05.mma.cta_group::1.kind::f16 [%0], %1, %2, %3, {%4, %4, %4, %4}, p;\n\t}"
        :: "r"(d), "l"(a), "l"(b), "r"(idesc), "r"(0u), "r"(en) : "memory");
}
#define TC_ALLOC(sl, n) asm volatile("tcgen05.alloc.cta_group::1.sync.aligned.shared::cta.b32 [%0], %1;" :: "r"(sl), "r"(n) : "memory")
#define TC_DEALLOC(tm, n) asm volatile("tcgen05.dealloc.cta_group::1.sync.aligned.b32 %0, %1;" :: "r"(tm), "r"(n))
#define TC_COMMIT(mb) asm volatile("tcgen05.commit.cta_group::1.mbarrier::arrive::one.shared::cluster.b64 [%0];" :: "r"(mb) : "memory")
#define TC_WAIT_LD() asm volatile("tcgen05.wait::ld.sync.aligned;" ::: "memory")
#define TC_WAIT_ST() asm volatile("tcgen05.wait::st.sync.aligned;" ::: "memory")
#define TC_FENCE_BEFORE() asm volatile("tcgen05.fence::before_thread_sync;" ::: "memory")
#define TC_FENCE_AFTER() asm volatile("tcgen05.fence::after_thread_sync;" ::: "memory")
#define FENCE_ASYNC() asm volatile("fence.proxy.async.shared::cta;" ::: "memory")
#define MBAR_INIT(mb, c) asm volatile("mbarrier.init.shared.b64 [%0], %1;" :: "r"(mb), "r"(c) : "memory")
#define MBAR_INVAL(mb) asm volatile("mbarrier.inval.shared.b64 [%0];" :: "r"(mb) : "memory")
#define MBAR_WAIT(mb, ph) do { \
    asm volatile( \
        "{\n\t.reg .pred P1;\n\t" \
        "WL_%=:\n\t" \
        "mbarrier.try_wait.parity.acquire.cta.shared::cta.b64 P1, [%0], %1, 0x989680;\n\t" \
        "@P1 bra.uni WD_%=;\n\t" \
        "bra.uni WL_%=;\n\t" \
        "WD_%=:\n\t}" :: "r"(mb), "r"(ph) : "memory"); \
} while (0)
#define LDTM32(r, a) \
    asm volatile("tcgen05.ld.sync.aligned.32x32b.x32.b32 " \
        "{%0, %1, %2, %3, %4, %5, %6, %7, %8, %9, %10, %11, %12, %13, %14, %15, " \
        " %16, %17, %18, %19, %20, %21, %22, %23, %24, %25, %26, %27, %28, %29, %30, %31}, [%32];" \
        : "=r"((r)[0]), "=r"((r)[1]), "=r"((r)[2]), "=r"((r)[3]), "=r"((r)[4]), "=r"((r)[5]), \
          "=r"((r)[6]), "=r"((r)[7]), "=r"((r)[8]), "=r"((r)[9]), "=r"((r)[10]), "=r"((r)[11]), \
          "=r"((r)[12]), "=r"((r)[13]), "=r"((r)[14]), "=r"((r)[15]), "=r"((r)[16]), "=r"((r)[17]), \
          "=r"((r)[18]), "=r"((r)[19]), "=r"((r)[20]), "=r"((r)[21]), "=r"((r)[22]), "=r"((r)[23]), \
          "=r"((r)[24]), "=r"((r)[25]), "=r"((r)[26]), "=r"((r)[27]), "=r"((r)[28]), "=r"((r)[29]), \
          "=r"((r)[30]), "=r"((r)[31]) : "r"(a))
#define STTM32(a, r) \
    asm volatile("tcgen05.st.sync.aligned.32x32b.x32.b32 [%0], " \
        "{%1, %2, %3, %4, %5, %6, %7, %8, %9, %10, %11, %12, %13, %14, %15, %16, " \
        " %17, %18, %19, %20, %21, %22, %23, %24, %25, %26, %27, %28, %29, %30, %31, %32};" \
        :: "r"(a), \
           "r"((r)[0]), "r"((r)[1]), "r"((r)[2]), "r"((r)[3]), "r"((r)[4]), "r"((r)[5]), \
           "r"((r)[6]), "r"((r)[7]), "r"((r)[8]), "r"((r)[9]), "r"((r)[10]), "r"((r)[11]), \
           "r"((r)[12]), "r"((r)[13]), "r"((r)[14]), "r"((r)[15]), "r"((r)[16]), "r"((r)[17]), \
           "r"((r)[18]), "r"((r)[19]), "r"((r)[20]), "r"((r)[21]), "r"((r)[22]), "r"((r)[23]), \
           "r"((r)[24]), "r"((r)[25]), "r"((r)[26]), "r"((r)[27]), "r"((r)[28]), "r"((r)[29]), \
           "r"((r)[30]), "r"((r)[31]) : "memory")
#endif  // HAS_TCGEN05

__global__ void zero_kernel(float4* __restrict__ out) {
    out[blockIdx.x * 256 + threadIdx.x] = make_float4(0.f, 0.f, 0.f, 0.f);
}

__global__ void split_weights_kernel(const float* __restrict__ W1,
                                     const float* __restrict__ W2) {
    const int t = blockIdx.x * 256 + threadIdx.x;
    if (t < 2048) {
        int n = t & 63, k = t >> 6;
        float v = W1[(size_t)(128 + k) * 64 + n];
        __nv_bfloat16 hi = __float2bfloat16(v);
        __nv_bfloat16 lo = __float2bfloat16(v - __bfloat162float(hi));
        int so = SW(n * 128 + k * 2);
        *(__nv_bfloat16*)(g_W1hi + so) = hi;
        *(__nv_bfloat16*)(g_W1lo + so) = lo;
    }
    if (t < 4096) {
        int n = t & 63, k = t >> 6;
        float v = W2[(size_t)k * 64 + n];
        __nv_bfloat16 hi = __float2bfloat16(v);
        __nv_bfloat16 lo = __float2bfloat16(v - __bfloat162float(hi));
        int so = SW(n * 128 + k * 2);
        *(__nv_bfloat16*)(g_W2hi + so) = hi;
        *(__nv_bfloat16*)(g_W2lo + so) = lo;
    }
}

__global__ void __launch_bounds__(128) pq_kernel(const float* __restrict__ x,
                                                 const float* __restrict__ W1) {
    const float* Wbase = W1 + (size_t)blockIdx.y * 64 * 64;
    float* dst = blockIdx.y ? g_Q : g_P;
    const int l = threadIdx.x & 31;
    const int warp = (blockIdx.x * 128 + threadIdx.x) >> 5;
    const int nwarps = gridDim.x * 4;

    unsigned long long w[64];
#pragma unroll
    for (int k = 0; k < 64; k++)
        w[k] = *(const unsigned long long*)(Wbase + k * 64 + 2 * l);

    for (int n = warp; n < N_NODES; n += nwarps) {
        const float4* xr = (const float4*)(x + (size_t)n * 64);
        unsigned long long aA = 0ULL, aB = 0ULL;
#pragma unroll
        for (int k4 = 0; k4 < 16; k4++) {
            float4 xv = __ldg(xr + k4);
            aA = ffma2(pack2(xv.x, xv.x), w[4 * k4 + 0], aA);
            aB = ffma2(pack2(xv.y, xv.y), w[4 * k4 + 1], aB);
            aA = ffma2(pack2(xv.z, xv.z), w[4 * k4 + 2], aA);
            aB = ffma2(pack2(xv.w, xv.w), w[4 * k4 + 3], aB);
        }
        *(unsigned long long*)(dst + (size_t)n * 64 + 2 * l) = fadd2(aA, aB);
    }
}

// ========== persistent edge kernel: 256 edges/tile, ~21 tiles/CTA ==========
__global__ void __launch_bounds__(256, 2) edge_kernel(
    const int* __restrict__ eidx, const float* __restrict__ eattr,
    const float* __restrict__ W1, const float* __restrict__ b1,
    const float* __restrict__ gamma_, const float* __restrict__ beta_,
    const float* __restrict__ W2, const float* __restrict__ b2,
    float* __restrict__ out) {
    extern __shared__ __align__(1024) char smem[];
    const int t = threadIdx.x;

#if HAS_TCGEN05
    // ======================= tcgen05 persistent path =======================
    const uint32_t sbase = smem_u32(smem);
    const int wg = t >> 7;
    const int r = t & 127;

    float* sB1 = (float*)(smem + SB1_OFF);
    float* sB2 = (float*)(smem + SB2_OFF);
    float* sG = (float*)(smem + SG_OFF);
    float* sBt = (float*)(smem + SBT_OFF);
    const uint32_t mbar = sbase + MBAR_OFF;
    char* aHi = smem + A_HI_OFF + wg * 16384;
    char* aLo = smem + A_LO_OFF + wg * 16384;

    // ---- one-time setup ----
    if (t < 32) TC_ALLOC(sbase + TMEMP_OFF, 128);
    {
        const uint4* w1h = (const uint4*)g_W1hi;
        const uint4* w1l = (const uint4*)g_W1lo;
        const uint4* w2h = (const uint4*)g_W2hi;
        const uint4* w2l = (const uint4*)g_W2lo;
#pragma unroll
        for (int i = t; i < 512; i += 256) {
            ((uint4*)(smem + BW1_HI_OFF))[i] = __ldg(w1h + i);
            ((uint4*)(smem + BW1_LO_OFF))[i] = __ldg(w1l + i);
            ((uint4*)(smem + BW2_HI_OFF))[i] = __ldg(w2h + i);
            ((uint4*)(smem + BW2_LO_OFF))[i] = __ldg(w2l + i);
        }
    }
    if (t < 64) { sB1[t] = b1[t]; sB2[t] = b2[t]; sG[t] = gamma_[t]; sBt[t] = beta_[t]; }
    if (t == 0) MBAR_INIT(mbar, 1);

    const uint64_t b1h = mk_desc(sbase + BW1_HI_OFF);
    const uint64_t b1l = mk_desc(sbase + BW1_LO_OFF);
    const uint64_t b2h = mk_desc(sbase + BW2_HI_OFF);
    const uint64_t b2l = mk_desc(sbase + BW2_LO_OFF);

    int tile = blockIdx.x;
    int vi = eidx[tile * 256 + t];
    int vj = eidx[N_EDGES + tile * 256 + t];

    // ---- stage first tile's eattr ----
    {
        const float4* ef = (const float4*)(eattr + (size_t)(tile * 256 + t) * 32);
#pragma unroll
        for (int c = 0; c < 4; c++) {
            float4 e0 = __ldg(ef + 2 * c);
            float4 e1 = __ldg(ef + 2 * c + 1);
            const float ev[8] = {e0.x, e0.y, e0.z, e0.w, e1.x, e1.y, e1.z, e1.w};
            uint32_t hw[4], lw[4];
#pragma unroll
            for (int p = 0; p < 4; p++) {
                float f0 = ev[2 * p], f1 = ev[2 * p + 1];
                __nv_bfloat16 h0 = __float2bfloat16(f0), h1 = __float2bfloat16(f1);
                hw[p] = ((uint32_t)__bfloat16_as_ushort(h1) << 16) | __bfloat16_as_ushort(h0);
                lw[p] = pack_bf16(f0 - __bfloat162float(h0), f1 - __bfloat162float(h1));
            }
            int so = SW(r * 128 + c * 16);
            *(uint4*)(aHi + so) = make_uint4(hw[0], hw[1], hw[2], hw[3]);
            *(uint4*)(aLo + so) = make_uint4(lw[0], lw[1], lw[2], lw[3]);
        }
    }
    FENCE_ASYNC();
    __syncthreads();

    uint32_t tmem;
    asm volatile("ld.shared.b32 %0, [%1];" : "=r"(tmem) : "r"(sbase + TMEMP_OFF));

    int ph = 0;
    for (; tile < N_TILES; ) {
        const int ntile = tile + GRID_PERSIST;
        const bool have_next = ntile < N_TILES;

        // ---- MMA1 ----
        if (t < 32 && elect_one()) {
#pragma unroll
            for (int tl = 0; tl < 2; tl++) {
                uint32_t dcol = tmem + tl * 64;
                uint64_t ah = mk_desc(sbase + A_HI_OFF + tl * 16384);
                uint64_t al = mk_desc(sbase + A_LO_OFF + tl * 16384);
                uint64_t ads[3] = {ah, al, ah};
                uint64_t bds[3] = {b1h, b1h, b1l};
#pragma unroll
                for (int term = 0; term < 3; term++)
#pragma unroll
                    for (int k = 0; k < 2; k++)
                        mma_f16_ss(dcol, ads[term] + k * 2, bds[term] + k * 2, IDESC,
                                   (term | k) != 0);
            }
            TC_COMMIT(mbar);
        }
        MBAR_WAIT(mbar, ph & 1);
        ph++;
        TC_FENCE_AFTER();

        // ---- prefetch next tile's indices + eattr into regs (latency hidden) ----
        int nvi = 0, nvj = 0;
        float4 pf[8];
        if (have_next) {
            nvi = eidx[ntile * 256 + t];
            nvj = eidx[N_EDGES + ntile * 256 + t];
            const float4* ef = (const float4*)(eattr + (size_t)(ntile * 256 + t) * 32);
#pragma unroll
            for (int i = 0; i < 8; i++) pf[i] = __ldg(ef + i);
        }

        // ---- epilogue 1 pass 1: h = D + P + Q + b1 ; LN stats ; h -> TMEM ----
        const float* Pr = g_P + (size_t)vi * 64;
        const float* Qr = g_Q + (size_t)vj * 64;
        float s = 0.f, ss = 0.f;
#pragma unroll
        for (int half = 0; half < 2; half++) {
            uint32_t d[32];
            LDTM32(d, tmem + wg * 64 + half * 32);
            TC_WAIT_LD();
#pragma unroll
            for (int c4 = 0; c4 < 8; c4++) {
                float4 p = __ldg((const float4*)Pr + half * 8 + c4);
                float4 q = __ldg((const float4*)Qr + half * 8 + c4);
                float4 bb = *(const float4*)(sB1 + half * 32 + 4 * c4);
                float v0 = __uint_as_float(d[4 * c4 + 0]) + p.x + q.x + bb.x;
                float v1 = __uint_as_float(d[4 * c4 + 1]) + p.y + q.y + bb.y;
                float v2 = __uint_as_float(d[4 * c4 + 2]) + p.z + q.z + bb.z;
                float v3 = __uint_as_float(d[4 * c4 + 3]) + p.w + q.w + bb.w;
                s += (v0 + v1) + (v2 + v3);
                ss += (v0 * v0 + v1 * v1) + (v2 * v2 + v3 * v3);
                d[4 * c4 + 0] = __float_as_uint(v0);
                d[4 * c4 + 1] = __float_as_uint(v1);
                d[4 * c4 + 2] = __float_as_uint(v2);
                d[4 * c4 + 3] = __float_as_uint(v3);
            }
            STTM32(tmem + wg * 64 + half * 32, d);
        }
        TC_WAIT_ST();

        const float mu = s * (1.0f / 64.0f);
        const float var = ss * (1.0f / 64.0f) - mu * mu;
        const float rstd = rsqrtf(var + 1e-5f);

        // ---- epilogue 1 pass 2: reload h, LN+GELU, split -> A tiles ----
#pragma unroll
        for (int half = 0; half < 2; half++) {
            uint32_t d[32];
            LDTM32(d, tmem + wg * 64 + half * 32);
            TC_WAIT_LD();
#pragma unroll
            for (int c = 0; c < 4; c++) {
                uint32_t hw[4], lw[4];
#pragma unroll
                for (int p = 0; p < 4; p++) {
                    int j = c * 8 + 2 * p;
                    int ch = half * 32 + j;
                    float u0 = (__uint_as_float(d[j]) - mu) * rstd * sG[ch] + sBt[ch];
                    float u1 = (__uint_as_float(d[j + 1]) - mu) * rstd * sG[ch + 1] + sBt[ch + 1];
                    float f0 = 0.5f * u0 * (1.0f + erff(u0 * 0.70710678118654752f));
                    float f1 = 0.5f * u1 * (1.0f + erff(u1 * 0.70710678118654752f));
                    __nv_bfloat16 h0 = __float2bfloat16(f0), h1 = __float2bfloat16(f1);
                    hw[p] = ((uint32_t)__bfloat16_as_ushort(h1) << 16) | __bfloat16_as_ushort(h0);
                    lw[p] = pack_bf16(f0 - __bfloat162float(h0), f1 - __bfloat162float(h1));
                }
                int so = SW(r * 128 + half * 64 + c * 16);
                *(uint4*)(aHi + so) = make_uint4(hw[0], hw[1], hw[2], hw[3]);
                *(uint4*)(aLo + so) = make_uint4(lw[0], lw[1], lw[2], lw[3]);
            }
        }
        TC_FENCE_BEFORE();
        FENCE_ASYNC();
        __syncthreads();

        // ---- MMA2 ----
        if (t < 32 && elect_one()) {
#pragma unroll
            for (int tl = 0; tl < 2; tl++) {
                uint32_t dcol = tmem + tl * 64;
                uint64_t ah = mk_desc(sbase + A_HI_OFF + tl * 16384);
                uint64_t al = mk_desc(sbase + A_LO_OFF + tl * 16384);
                uint64_t ads[3] = {ah, al, ah};
                uint64_t bds[3] = {b2h, b2h, b2l};
#pragma unroll
                for (int term = 0; term < 3; term++)
#pragma unroll
                    for (int k = 0; k < 4; k++)
                        mma_f16_ss(dcol, ads[term] + k * 2, bds[term] + k * 2, IDESC,
                                   (term | k) != 0);
            }
            TC_COMMIT(mbar);
        }
        MBAR_WAIT(mbar, ph & 1);
        ph++;
        TC_FENCE_AFTER();

        // ---- epilogue 2: D + b2, scatter-add ----
        {
            float* op = out + (size_t)vj * 64;
#pragma unroll
            for (int half = 0; half < 2; half++) {
                uint32_t d[32];
                LDTM32(d, tmem + wg * 64 + half * 32);
                TC_WAIT_LD();
#pragma unroll
                for (int c4 = 0; c4 < 8; c4++) {
                    float4 bb = *(const float4*)(sB2 + half * 32 + 4 * c4);
                    red4(op + half * 32 + 4 * c4,
                         __uint_as_float(d[4 * c4 + 0]) + bb.x,
                         __uint_as_float(d[4 * c4 + 1]) + bb.y,
                         __uint_as_float(d[4 * c4 + 2]) + bb.z,
                         __uint_as_float(d[4 * c4 + 3]) + bb.w);
                }
            }
        }

        // ---- stage next tile's eattr (A tiles free: MMA2 completion waited) ----
        if (have_next) {
#pragma unroll
            for (int c = 0; c < 4; c++) {
                const float ev[8] = {pf[2 * c].x, pf[2 * c].y, pf[2 * c].z, pf[2 * c].w,
                                     pf[2 * c + 1].x, pf[2 * c + 1].y, pf[2 * c + 1].z,
                                     pf[2 * c + 1].w};
                uint32_t hw[4], lw[4];
#pragma unroll
                for (int p = 0; p < 4; p++) {
                    float f0 = ev[2 * p], f1 = ev[2 * p + 1];
                    __nv_bfloat16 h0 = __float2bfloat16(f0), h1 = __float2bfloat16(f1);
                    hw[p] = ((uint32_t)__bfloat16_as_ushort(h1) << 16) | __bfloat16_as_ushort(h0);
                    lw[p] = pack_bf16(f0 - __bfloat162float(h0), f1 - __bfloat162float(h1));
                }
                int so = SW(r * 128 + c * 16);
                *(uint4*)(aHi + so) = make_uint4(hw[0], hw[1], hw[2], hw[3]);
                *(uint4*)(aLo + so) = make_uint4(lw[0], lw[1], lw[2], lw[3]);
            }
            vi = nvi;
            vj = nvj;
        }
        FENCE_ASYNC();
        __syncthreads();
        tile = ntile;
    }

    if (t == 0) MBAR_INVAL(mbar);
    __syncthreads();
    if (t < 32) TC_DEALLOC(tmem, 128);

#else
    // ======================= scalar fallback (R3, persistent loop) ==========
    float* sH = (float*)(smem + F_H_OFF);
    float* sW1c = (float*)(smem + F_W1C_OFF);
    float* sW2 = (float*)(smem + F_W2_OFF);
    int* sIi = (int*)(smem + F_II_OFF);
    int* sIj = (int*)(smem + F_IJ_OFF);
    float* sB1 = (float*)(smem + F_B_OFF);
    float* sB2 = sB1 + 64;
    float* sG = sB1 + 128;
    float* sBt = sB1 + 192;

    const int tr = t >> 3;
    const int tc = t & 7;

    {
        const float4* w1s = (const float4*)(W1 + 128 * 64);
#pragma unroll
        for (int i = 0; i < 2; i++) ((float4*)sW1c)[t + 256 * i] = w1s[t + 256 * i];
        const float4* w2s = (const float4*)W2;
#pragma unroll
        for (int i = 0; i < 4; i++) ((float4*)sW2)[t + 256 * i] = w2s[t + 256 * i];
        if (t < 64) { sB1[t] = b1[t]; sB2[t] = b2[t]; sG[t] = gamma_[t]; sBt[t] = beta_[t]; }
    }

    for (int tile = blockIdx.x; tile < N_TILES; tile += GRID_PERSIST) {
        const int Eb = tile * 256;
        __syncthreads();
        sIi[t] = eidx[Eb + t];
        sIj[t] = eidx[N_EDGES + Eb + t];
        {
            const float4* er = (const float4*)(eattr + (size_t)(Eb + t) * 32);
            float4 ev[8];
#pragma unroll
            for (int i = 0; i < 8; i++) ev[i] = __ldg(er + i);
            const float* evf = (const float*)ev;
            const int ecbase = t >> 3, off = t & 7;
#pragma unroll
            for (int k = 0; k < 32; k++)
                sH[k * 256 + ((ecbase ^ (k >> 3)) & 31) * 8 + off] = evf[k];
        }
        __syncthreads();

        unsigned long long acc[8][4];
        {
            float4 b1a = *(const float4*)(sB1 + tc * 8);
            float4 b1b = *(const float4*)(sB1 + tc * 8 + 4);
#pragma unroll
            for (int e = 0; e < 8; e++) {
                const int vi = sIi[tr * 8 + e];
                const int vj = sIj[tr * 8 + e];
                const float* Pr = g_P + (size_t)vi * 64 + tc * 8;
                const float* Qr = g_Q + (size_t)vj * 64 + tc * 8;
                float4 pa = *(const float4*)Pr;
                float4 pb = *(const float4*)(Pr + 4);
                float4 qa = *(const float4*)Qr;
                float4 qb = *(const float4*)(Qr + 4);
                acc[e][0] = pack2(pa.x + qa.x + b1a.x, pa.y + qa.y + b1a.y);
                acc[e][1] = pack2(pa.z + qa.z + b1a.z, pa.w + qa.w + b1a.w);
                acc[e][2] = pack2(pb.x + qb.x + b1b.x, pb.y + qb.y + b1b.y);
                acc[e][3] = pack2(pb.z + qb.z + b1b.z, pb.w + qb.w + b1b.w);
            }
        }
#pragma unroll
        for (int k = 0; k < 32; k++) {
            const float* arow = sH + k * 256 + ((tr ^ (k >> 3)) & 31) * 8;
            float4 a0 = *(const float4*)arow;
            float4 a1 = *(const float4*)(arow + 4);
            const ulonglong2 w0 = *(const ulonglong2*)(sW1c + k * 64 + tc * 8);
            const ulonglong2 w1 = *(const ulonglong2*)(sW1c + k * 64 + tc * 8 + 4);
            const float a[8] = {a0.x, a0.y, a0.z, a0.w, a1.x, a1.y, a1.z, a1.w};
#pragma unroll
            for (int e = 0; e < 8; e++) {
                unsigned long long ae = pack2(a[e], a[e]);
                acc[e][0] = ffma2(ae, w0.x, acc[e][0]);
                acc[e][1] = ffma2(ae, w0.y, acc[e][1]);
                acc[e][2] = ffma2(ae, w1.x, acc[e][2]);
                acc[e][3] = ffma2(ae, w1.y, acc[e][3]);
            }
        }

        float s[8], ss[8];
#pragma unroll
        for (int e = 0; e < 8; e++) {
            float h0, h1, h2, h3, h4, h5, h6, h7;
            unpack2(acc[e][0], h0, h1); unpack2(acc[e][1], h2, h3);
            unpack2(acc[e][2], h4, h5); unpack2(acc[e][3], h6, h7);
            s[e] = ((h0 + h1) + (h2 + h3)) + ((h4 + h5) + (h6 + h7));
            ss[e] = ((h0 * h0 + h1 * h1) + (h2 * h2 + h3 * h3)) +
                    ((h4 * h4 + h5 * h5) + (h6 * h6 + h7 * h7));
        }
#pragma unroll
        for (int m = 1; m < 8; m <<= 1) {
#pragma unroll
            for (int e = 0; e < 8; e++) {
                s[e] += __shfl_xor_sync(0xffffffffu, s[e], m);
                ss[e] += __shfl_xor_sync(0xffffffffu, ss[e], m);
            }
        }

        float4 ga = *(const float4*)(sG + tc * 8);
        float4 gb = *(const float4*)(sG + tc * 8 + 4);
        float4 ba = *(const float4*)(sBt + tc * 8);
        float4 bb = *(const float4*)(sBt + tc * 8 + 4);
        const float gg[8] = {ga.x, ga.y, ga.z, ga.w, gb.x, gb.y, gb.z, gb.w};
        const float bt[8] = {ba.x, ba.y, ba.z, ba.w, bb.x, bb.y, bb.z, bb.w};

        __syncthreads();

#pragma unroll
        for (int e = 0; e < 8; e++) {
            const float mu = s[e] * (1.0f / 64.0f);
            const float var = ss[e] * (1.0f / 64.0f) - mu * mu;
            const float rstd = rsqrtf(var + 1e-5f);
            float h[8];
            unpack2(acc[e][0], h[0], h[1]); unpack2(acc[e][1], h[2], h[3]);
            unpack2(acc[e][2], h[4], h[5]); unpack2(acc[e][3], h[6], h[7]);
#pragma unroll
            for (int c = 0; c < 8; c++) {
                float v = (h[c] - mu) * rstd * gg[c] + bt[c];
                h[c] = 0.5f * v * (1.0f + erff(v * 0.70710678118654752f));
            }
#pragma unroll
            for (int c = 0; c < 8; c++)
                sH[(tc * 8 + c) * 256 + ((tr ^ tc) & 31) * 8 + e] = h[c];
        }
        __syncthreads();

        {
            float4 b2a = *(const float4*)(sB2 + tc * 8);
            float4 b2b = *(const float4*)(sB2 + tc * 8 + 4);
#pragma unroll
            for (int e = 0; e < 8; e++) {
                acc[e][0] = pack2(b2a.x, b2a.y);
                acc[e][1] = pack2(b2a.z, b2a.w);
                acc[e][2] = pack2(b2b.x, b2b.y);
                acc[e][3] = pack2(b2b.z, b2b.w);
            }
        }
#pragma unroll
        for (int k = 0; k < 64; k++) {
            const float* arow = sH + k * 256 + ((tr ^ (k >> 3)) & 31) * 8;
            float4 a0 = *(const float4*)arow;
            float4 a1 = *(const float4*)(arow + 4);
            const ulonglong2 w0 = *(const ulonglong2*)(sW2 + k * 64 + tc * 8);
            const ulonglong2 w1 = *(const ulonglong2*)(sW2 + k * 64 + tc * 8 + 4);
            const float a[8] = {a0.x, a0.y, a0.z, a0.w, a1.x, a1.y, a1.z, a1.w};
#pragma unroll
            for (int e = 0; e < 8; e++) {
                unsigned long long ae = pack2(a[e], a[e]);
                acc[e][0] = ffma2(ae, w0.x, acc[e][0]);
                acc[e][1] = ffma2(ae, w0.y, acc[e][1]);
                acc[e][2] = ffma2(ae, w1.x, acc[e][2]);
                acc[e][3] = ffma2(ae, w1.y, acc[e][3]);
            }
        }

#pragma unroll
        for (int e = 0; e < 8; e++) {
            const int vj = sIj[tr * 8 + e];
            float* op = out + (size_t)vj * 64 + tc * 8;
            float m0, m1, m2, m3, m4, m5, m6, m7;
            unpack2(acc[e][0], m0, m1); unpack2(acc[e][1], m2, m3);
            unpack2(acc[e][2], m4, m5); unpack2(acc[e][3], m6, m7);
            red4(op, m0, m1, m2, m3);
            red4(op + 4, m4, m5, m6, m7);
        }
    }
#endif
}

extern "C" void kernel_launch(void* const* d_in, const int* in_sizes, int n_in,
                              void* d_out, int out_size) {
    const float* x = (const float*)d_in[0];
    const int* eidx = (const int*)d_in[1];
    const float* eattr = (const float*)d_in[2];
    const float* W1 = (const float*)d_in[3];
    const float* b1 = (const float*)d_in[4];
    const float* gamma_ = (const float*)d_in[5];
    const float* beta_ = (const float*)d_in[6];
    const float* W2 = (const float*)d_in[7];
    const float* b2 = (const float*)d_in[8];
    float* out = (float*)d_out;

    cudaFuncSetAttribute(edge_kernel, cudaFuncAttributeMaxDynamicSharedMemorySize, SMEM_TOTAL);

    zero_kernel<<<6250, 256>>>((float4*)out);
    split_weights_kernel<<<16, 256>>>(W1, W2);
    pq_kernel<<<dim3(1024, 2), 128>>>(x, W1);
    edge_kernel<<<GRID_PERSIST, 256, SMEM_TOTAL>>>(eidx, eattr, W1, b1, gamma_, beta_, W2, b2,
                                                   out);
}

// round 15
// speedup vs baseline: 1.1979x; 1.0053x over previous
#include <cuda_runtime.h>
#include <cuda_bf16.h>
#include <cstdint>

#define N_NODES 100000
#define N_EDGES 1600000
#define N_TILES 6250          // scalar fallback: 256-edge tiles
#define N_WGTILES 12500       // tensor path: 128-edge WG-tiles
#define GRID_PERSIST 296
#define N_PIPES (GRID_PERSIST * 2)

__device__ float g_P[N_NODES * 64];
__device__ float g_Q[N_NODES * 64];
__device__ __align__(16) uint8_t g_W1hi[8192], g_W1lo[8192];
__device__ __align__(16) uint8_t g_W2hi[8192], g_W2lo[8192];

#if defined(__CUDA_ARCH_FEAT_SM103_ALL) || defined(__CUDA_ARCH_FEAT_SM100_ALL) || defined(__CUDA_ARCH_FEAT_SM101_ALL)
#define HAS_TCGEN05 1
#else
#define HAS_TCGEN05 0
#endif

// ---------------- tensor-path smem layout ----------------
#define A_HI_OFF   0
#define A_LO_OFF   32768
#define BW1_HI_OFF 65536
#define BW1_LO_OFF 73728
#define BW2_HI_OFF 81920
#define BW2_LO_OFF 90112
#define TMEMP_OFF  98304
#define MBAR_OFF   98312      // 2 mbarriers (8B each)
#define SB1_OFF    98368
#define SB2_OFF    98624
#define SG_OFF     98880
#define SBT_OFF    99136
#define SMEM_TOTAL 99840

// ---------------- scalar-fallback smem layout ----------------
#define F_H_OFF    0
#define F_W1C_OFF  65536
#define F_W2_OFF   73728
#define F_II_OFF   90112
#define F_IJ_OFF   91136
#define F_B_OFF    92160

#define IDESC 0x8100490u
#define SW(o) ((o) ^ (((o) >> 3) & 0x70))

static __device__ __forceinline__ uint32_t smem_u32(const void* p) {
    uint32_t a;
    asm("{ .reg .u64 t; cvta.to.shared.u64 t, %1; cvt.u32.u64 %0, t; }" : "=r"(a) : "l"(p));
    return a;
}
static __device__ __forceinline__ void red4(float* p, float a, float b, float c, float d) {
    asm volatile("red.global.add.v4.f32 [%0], {%1, %2, %3, %4};"
                 :: "l"(p), "f"(a), "f"(b), "f"(c), "f"(d) : "memory");
}
static __device__ __forceinline__ unsigned long long pack2(float a, float b) {
    unsigned long long r;
    asm("mov.b64 %0, {%1, %2};" : "=l"(r) : "f"(a), "f"(b));
    return r;
}
static __device__ __forceinline__ void unpack2(unsigned long long v, float& a, float& b) {
    asm("mov.b64 {%0, %1}, %2;" : "=f"(a), "=f"(b) : "l"(v));
}
static __device__ __forceinline__ unsigned long long ffma2(unsigned long long a,
                                                           unsigned long long b,
                                                           unsigned long long c) {
    unsigned long long d;
    asm("fma.rn.f32x2 %0, %1, %2, %3;" : "=l"(d) : "l"(a), "l"(b), "l"(c));
    return d;
}
static __device__ __forceinline__ unsigned long long fadd2(unsigned long long a,
                                                           unsigned long long b) {
    unsigned long long d;
    asm("add.rn.f32x2 %0, %1, %2;" : "=l"(d) : "l"(a), "l"(b));
    return d;
}
static __device__ __forceinline__ uint32_t pack_bf16(float f0, float f1) {
    __nv_bfloat16 h0 = __float2bfloat16(f0);
    __nv_bfloat16 h1 = __float2bfloat16(f1);
    return ((uint32_t)__bfloat16_as_ushort(h1) << 16) | (uint32_t)__bfloat16_as_ushort(h0);
}

#if HAS_TCGEN05
static __device__ __forceinline__ uint32_t elect_one() {
    uint32_t p;
    asm volatile("{\n\t.reg .pred p;\n\telect.sync _|p, 0xFFFFFFFF;\n\tselp.b32 %0, 1, 0, p;\n\t}" : "=r"(p));
    return p;
}
static __device__ __forceinline__ uint64_t mk_desc(uint32_t addr) {
    const uint64_t base = (2ULL << 61) | (1ULL << 46) | (64ULL << 32) | (1ULL << 16);
    return base | ((uint64_t)(addr >> 4) & 0x3FFF);
}
static __device__ __forceinline__ void mma_f16_ss(uint32_t d, uint64_t a, uint64_t b,
                                                  uint32_t idesc, int en) {
    asm volatile(
        "{\n\t.reg .pred p;\n\tsetp.ne.u32 p, %5, 0;\n\t"
        "tcgen05.mma.cta_group::1.kind::f16 [%0], %1, %2, %3, {%4, %4, %4, %4}, p;\n\t}"
        :: "r"(d), "l"(a), "l"(b), "r"(idesc), "r"(0u), "r"(en) : "memory");
}
#define TC_ALLOC(sl, n) asm volatile("tcgen05.alloc.cta_group::1.sync.aligned.shared::cta.b32 [%0], %1;" :: "r"(sl), "r"(n) : "memory")
#define TC_DEALLOC(tm, n) asm volatile("tcgen05.dealloc.cta_group::1.sync.aligned.b32 %0, %1;" :: "r"(tm), "r"(n))
#define TC_COMMIT(mb) asm volatile("tcgen05.commit.cta_group::1.mbarrier::arrive::one.shared::cluster.b64 [%0];" :: "r"(mb) : "memory")
#define TC_WAIT_LD() asm volatile("tcgen05.wait::ld.sync.aligned;" ::: "memory")
#define TC_WAIT_ST() asm volatile("tcgen05.wait::st.sync.aligned;" ::: "memory")
#define TC_FENCE_BEFORE() asm volatile("tcgen05.fence::before_thread_sync;" ::: "memory")
#define TC_FENCE_AFTER() asm volatile("tcgen05.fence::after_thread_sync;" ::: "memory")
#define FENCE_ASYNC() asm volatile("fence.proxy.async.shared::cta;" ::: "memory")
#define WG_SYNC(id) asm volatile("bar.sync %0, 128;" :: "r"(id) : "memory")
#define MBAR_INIT(mb, c) asm volatile("mbarrier.init.shared.b64 [%0], %1;" :: "r"(mb), "r"(c) : "memory")
#define MBAR_INVAL(mb) asm volatile("mbarrier.inval.shared.b64 [%0];" :: "r"(mb) : "memory")
#define MBAR_WAIT(mb, ph) do { \
    asm volatile( \
        "{\n\t.reg .pred P1;\n\t" \
        "WL_%=:\n\t" \
        "mbarrier.try_wait.parity.acquire.cta.shared::cta.b64 P1, [%0], %1, 0x989680;\n\t" \
        "@P1 bra.uni WD_%=;\n\t" \
        "bra.uni WL_%=;\n\t" \
        "WD_%=:\n\t}" :: "r"(mb), "r"(ph) : "memory"); \
} while (0)
#define LDTM32(r, a) \
    asm volatile("tcgen05.ld.sync.aligned.32x32b.x32.b32 " \
        "{%0, %1, %2, %3, %4, %5, %6, %7, %8, %9, %10, %11, %12, %13, %14, %15, " \
        " %16, %17, %18, %19, %20, %21, %22, %23, %24, %25, %26, %27, %28, %29, %30, %31}, [%32];" \
        : "=r"((r)[0]), "=r"((r)[1]), "=r"((r)[2]), "=r"((r)[3]), "=r"((r)[4]), "=r"((r)[5]), \
          "=r"((r)[6]), "=r"((r)[7]), "=r"((r)[8]), "=r"((r)[9]), "=r"((r)[10]), "=r"((r)[11]), \
          "=r"((r)[12]), "=r"((r)[13]), "=r"((r)[14]), "=r"((r)[15]), "=r"((r)[16]), "=r"((r)[17]), \
          "=r"((r)[18]), "=r"((r)[19]), "=r"((r)[20]), "=r"((r)[21]), "=r"((r)[22]), "=r"((r)[23]), \
          "=r"((r)[24]), "=r"((r)[25]), "=r"((r)[26]), "=r"((r)[27]), "=r"((r)[28]), "=r"((r)[29]), \
          "=r"((r)[30]), "=r"((r)[31]) : "r"(a))
#define STTM32(a, r) \
    asm volatile("tcgen05.st.sync.aligned.32x32b.x32.b32 [%0], " \
        "{%1, %2, %3, %4, %5, %6, %7, %8, %9, %10, %11, %12, %13, %14, %15, %16, " \
        " %17, %18, %19, %20, %21, %22, %23, %24, %25, %26, %27, %28, %29, %30, %31, %32};" \
        :: "r"(a), \
           "r"((r)[0]), "r"((r)[1]), "r"((r)[2]), "r"((r)[3]), "r"((r)[4]), "r"((r)[5]), \
           "r"((r)[6]), "r"((r)[7]), "r"((r)[8]), "r"((r)[9]), "r"((r)[10]), "r"((r)[11]), \
           "r"((r)[12]), "r"((r)[13]), "r"((r)[14]), "r"((r)[15]), "r"((r)[16]), "r"((r)[17]), \
           "r"((r)[18]), "r"((r)[19]), "r"((r)[20]), "r"((r)[21]), "r"((r)[22]), "r"((r)[23]), \
           "r"((r)[24]), "r"((r)[25]), "r"((r)[26]), "r"((r)[27]), "r"((r)[28]), "r"((r)[29]), \
           "r"((r)[30]), "r"((r)[31]) : "memory")
#endif  // HAS_TCGEN05

__global__ void zero_kernel(float4* __restrict__ out) {
    out[blockIdx.x * 256 + threadIdx.x] = make_float4(0.f, 0.f, 0.f, 0.f);
}

__global__ void split_weights_kernel(const float* __restrict__ W1,
                                     const float* __restrict__ W2) {
    const int t = blockIdx.x * 256 + threadIdx.x;
    if (t < 2048) {
        int n = t & 63, k = t >> 6;
        float v = W1[(size_t)(128 + k) * 64 + n];
        __nv_bfloat16 hi = __float2bfloat16(v);
        __nv_bfloat16 lo = __float2bfloat16(v - __bfloat162float(hi));
        int so = SW(n * 128 + k * 2);
        *(__nv_bfloat16*)(g_W1hi + so) = hi;
        *(__nv_bfloat16*)(g_W1lo + so) = lo;
    }
    if (t < 4096) {
        int n = t & 63, k = t >> 6;
        float v = W2[(size_t)k * 64 + n];
        __nv_bfloat16 hi = __float2bfloat16(v);
        __nv_bfloat16 lo = __float2bfloat16(v - __bfloat162float(hi));
        int so = SW(n * 128 + k * 2);
        *(__nv_bfloat16*)(g_W2hi + so) = hi;
        *(__nv_bfloat16*)(g_W2lo + so) = lo;
    }
}

__global__ void __launch_bounds__(128) pq_kernel(const float* __restrict__ x,
                                                 const float* __restrict__ W1) {
    const float* Wbase = W1 + (size_t)blockIdx.y * 64 * 64;
    float* dst = blockIdx.y ? g_Q : g_P;
    const int l = threadIdx.x & 31;
    const int warp = (blockIdx.x * 128 + threadIdx.x) >> 5;
    const int nwarps = gridDim.x * 4;

    unsigned long long w[64];
#pragma unroll
    for (int k = 0; k < 64; k++)
        w[k] = *(const unsigned long long*)(Wbase + k * 64 + 2 * l);

    for (int n = warp; n < N_NODES; n += nwarps) {
        const float4* xr = (const float4*)(x + (size_t)n * 64);
        unsigned long long aA = 0ULL, aB = 0ULL;
#pragma unroll
        for (int k4 = 0; k4 < 16; k4++) {
            float4 xv = __ldg(xr + k4);
            aA = ffma2(pack2(xv.x, xv.x), w[4 * k4 + 0], aA);
            aB = ffma2(pack2(xv.y, xv.y), w[4 * k4 + 1], aB);
            aA = ffma2(pack2(xv.z, xv.z), w[4 * k4 + 2], aA);
            aB = ffma2(pack2(xv.w, xv.w), w[4 * k4 + 3], aB);
        }
        *(unsigned long long*)(dst + (size_t)n * 64 + 2 * l) = fadd2(aA, aB);
    }
}

// ==== persistent edge kernel: 2 INDEPENDENT WG pipelines per CTA, 128 edges/WG-tile ====
__global__ void __launch_bounds__(256, 2) edge_kernel(
    const int* __restrict__ eidx, const float* __restrict__ eattr,
    const float* __restrict__ W1, const float* __restrict__ b1,
    const float* __restrict__ gamma_, const float* __restrict__ beta_,
    const float* __restrict__ W2, const float* __restrict__ b2,
    float* __restrict__ out) {
    extern __shared__ __align__(1024) char smem[];
    const int t = threadIdx.x;

#if HAS_TCGEN05
    // ======================= tcgen05 per-WG pipelines =======================
    const uint32_t sbase = smem_u32(smem);
    const int wg = t >> 7;      // 0 or 1: independent pipeline
    const int r = t & 127;      // row in this WG's M=128 tile

    float* sB1 = (float*)(smem + SB1_OFF);
    float* sB2 = (float*)(smem + SB2_OFF);
    float* sG = (float*)(smem + SG_OFF);
    float* sBt = (float*)(smem + SBT_OFF);
    const uint32_t mbar = sbase + MBAR_OFF + wg * 8;
    char* aHi = smem + A_HI_OFF + wg * 16384;
    char* aLo = smem + A_LO_OFF + wg * 16384;
    const int barid = 1 + wg;

    // ---- one-time setup (CTA-wide) ----
    if (t < 32) TC_ALLOC(sbase + TMEMP_OFF, 128);
    {
        const uint4* w1h = (const uint4*)g_W1hi;
        const uint4* w1l = (const uint4*)g_W1lo;
        const uint4* w2h = (const uint4*)g_W2hi;
        const uint4* w2l = (const uint4*)g_W2lo;
#pragma unroll
        for (int i = t; i < 512; i += 256) {
            ((uint4*)(smem + BW1_HI_OFF))[i] = __ldg(w1h + i);
            ((uint4*)(smem + BW1_LO_OFF))[i] = __ldg(w1l + i);
            ((uint4*)(smem + BW2_HI_OFF))[i] = __ldg(w2h + i);
            ((uint4*)(smem + BW2_LO_OFF))[i] = __ldg(w2l + i);
        }
    }
    if (t < 64) { sB1[t] = b1[t]; sB2[t] = b2[t]; sG[t] = gamma_[t]; sBt[t] = beta_[t]; }
    if (t == 0) {
        MBAR_INIT(sbase + MBAR_OFF, 1);
        MBAR_INIT(sbase + MBAR_OFF + 8, 1);
    }

    const uint64_t b1h = mk_desc(sbase + BW1_HI_OFF);
    const uint64_t b1l = mk_desc(sbase + BW1_LO_OFF);
    const uint64_t b2h = mk_desc(sbase + BW2_HI_OFF);
    const uint64_t b2l = mk_desc(sbase + BW2_LO_OFF);
    const uint64_t ah = mk_desc(sbase + A_HI_OFF + wg * 16384);
    const uint64_t al = mk_desc(sbase + A_LO_OFF + wg * 16384);

    int tile = blockIdx.x * 2 + wg;          // WG-tile of 128 edges
    int vi = eidx[tile * 128 + r];
    int vj = eidx[N_EDGES + tile * 128 + r];

    // ---- stage first tile's eattr ----
    {
        const float4* ef = (const float4*)(eattr + (size_t)(tile * 128 + r) * 32);
#pragma unroll
        for (int c = 0; c < 4; c++) {
            float4 e0 = __ldg(ef + 2 * c);
            float4 e1 = __ldg(ef + 2 * c + 1);
            const float ev[8] = {e0.x, e0.y, e0.z, e0.w, e1.x, e1.y, e1.z, e1.w};
            uint32_t hw[4], lw[4];
#pragma unroll
            for (int p = 0; p < 4; p++) {
                float f0 = ev[2 * p], f1 = ev[2 * p + 1];
                __nv_bfloat16 h0 = __float2bfloat16(f0), h1 = __float2bfloat16(f1);
                hw[p] = ((uint32_t)__bfloat16_as_ushort(h1) << 16) | __bfloat16_as_ushort(h0);
                lw[p] = pack_bf16(f0 - __bfloat162float(h0), f1 - __bfloat162float(h1));
            }
            int so = SW(r * 128 + c * 16);
            *(uint4*)(aHi + so) = make_uint4(hw[0], hw[1], hw[2], hw[3]);
            *(uint4*)(aLo + so) = make_uint4(lw[0], lw[1], lw[2], lw[3]);
        }
    }
    FENCE_ASYNC();
    __syncthreads();   // setup + alloc + mbar init + first staging all visible

    uint32_t tmem;
    asm volatile("ld.shared.b32 %0, [%1];" : "=r"(tmem) : "r"(sbase + TMEMP_OFF));
    const uint32_t dcol = tmem + wg * 64;

    int ph = 0;
    for (; tile < N_WGTILES; ) {
        const int ntile = tile + N_PIPES;
        const bool have_next = ntile < N_WGTILES;

        // ---- MMA1 (this WG's tile only; issued by WG's warp 0) ----
        if ((t & 127) < 32 && elect_one()) {
            uint64_t ads[3] = {ah, al, ah};
            uint64_t bds[3] = {b1h, b1h, b1l};
#pragma unroll
            for (int term = 0; term < 3; term++)
#pragma unroll
                for (int k = 0; k < 2; k++)
                    mma_f16_ss(dcol, ads[term] + k * 2, bds[term] + k * 2, IDESC,
                               (term | k) != 0);
            TC_COMMIT(mbar);
        }
        MBAR_WAIT(mbar, ph & 1);
        ph++;
        TC_FENCE_AFTER();

        // ---- prefetch next tile (latency hidden behind epilogue) ----
        int nvi = 0, nvj = 0;
        float4 pf[8];
        if (have_next) {
            nvi = eidx[ntile * 128 + r];
            nvj = eidx[N_EDGES + ntile * 128 + r];
            const float4* ef = (const float4*)(eattr + (size_t)(ntile * 128 + r) * 32);
#pragma unroll
            for (int i = 0; i < 8; i++) pf[i] = __ldg(ef + i);
        }

        // ---- epilogue 1 pass 1: h = D + P + Q + b1 ; LN stats ; h -> TMEM ----
        const float* Pr = g_P + (size_t)vi * 64;
        const float* Qr = g_Q + (size_t)vj * 64;
        float s = 0.f, ss = 0.f;
#pragma unroll
        for (int half = 0; half < 2; half++) {
            uint32_t d[32];
            LDTM32(d, dcol + half * 32);
            TC_WAIT_LD();
#pragma unroll
            for (int c4 = 0; c4 < 8; c4++) {
                float4 p = __ldg((const float4*)Pr + half * 8 + c4);
                float4 q = __ldg((const float4*)Qr + half * 8 + c4);
                float4 bb = *(const float4*)(sB1 + half * 32 + 4 * c4);
                float v0 = __uint_as_float(d[4 * c4 + 0]) + p.x + q.x + bb.x;
                float v1 = __uint_as_float(d[4 * c4 + 1]) + p.y + q.y + bb.y;
                float v2 = __uint_as_float(d[4 * c4 + 2]) + p.z + q.z + bb.z;
                float v3 = __uint_as_float(d[4 * c4 + 3]) + p.w + q.w + bb.w;
                s += (v0 + v1) + (v2 + v3);
                ss += (v0 * v0 + v1 * v1) + (v2 * v2 + v3 * v3);
                d[4 * c4 + 0] = __float_as_uint(v0);
                d[4 * c4 + 1] = __float_as_uint(v1);
                d[4 * c4 + 2] = __float_as_uint(v2);
                d[4 * c4 + 3] = __float_as_uint(v3);
            }
            STTM32(dcol + half * 32, d);
        }
        TC_WAIT_ST();

        const float mu = s * (1.0f / 64.0f);
        const float var = ss * (1.0f / 64.0f) - mu * mu;
        const float rstd = rsqrtf(var + 1e-5f);

        // ---- epilogue 1 pass 2: reload h, LN+GELU, split -> A tile ----
#pragma unroll
        for (int half = 0; half < 2; half++) {
            uint32_t d[32];
            LDTM32(d, dcol + half * 32);
            TC_WAIT_LD();
#pragma unroll
            for (int c = 0; c < 4; c++) {
                uint32_t hw[4], lw[4];
#pragma unroll
                for (int p = 0; p < 4; p++) {
                    int j = c * 8 + 2 * p;
                    int ch = half * 32 + j;
                    float u0 = (__uint_as_float(d[j]) - mu) * rstd * sG[ch] + sBt[ch];
                    float u1 = (__uint_as_float(d[j + 1]) - mu) * rstd * sG[ch + 1] + sBt[ch + 1];
                    float f0 = 0.5f * u0 * (1.0f + erff(u0 * 0.70710678118654752f));
                    float f1 = 0.5f * u1 * (1.0f + erff(u1 * 0.70710678118654752f));
                    __nv_bfloat16 h0 = __float2bfloat16(f0), h1 = __float2bfloat16(f1);
                    hw[p] = ((uint32_t)__bfloat16_as_ushort(h1) << 16) | __bfloat16_as_ushort(h0);
                    lw[p] = pack_bf16(f0 - __bfloat162float(h0), f1 - __bfloat162float(h1));
                }
                int so = SW(r * 128 + half * 64 + c * 16);
                *(uint4*)(aHi + so) = make_uint4(hw[0], hw[1], hw[2], hw[3]);
                *(uint4*)(aLo + so) = make_uint4(lw[0], lw[1], lw[2], lw[3]);
            }
        }
        TC_FENCE_BEFORE();
        FENCE_ASYNC();
        WG_SYNC(barid);

        // ---- MMA2 ----
        if ((t & 127) < 32 && elect_one()) {
            uint64_t ads[3] = {ah, al, ah};
            uint64_t bds[3] = {b2h, b2h, b2l};
#pragma unroll
            for (int term = 0; term < 3; term++)
#pragma unroll
                for (int k = 0; k < 4; k++)
                    mma_f16_ss(dcol, ads[term] + k * 2, bds[term] + k * 2, IDESC,
                               (term | k) != 0);
            TC_COMMIT(mbar);
        }
        MBAR_WAIT(mbar, ph & 1);
        ph++;
        TC_FENCE_AFTER();

        // ---- epilogue 2: D + b2, scatter-add ----
        {
            float* op = out + (size_t)vj * 64;
#pragma unroll
            for (int half = 0; half < 2; half++) {
                uint32_t d[32];
                LDTM32(d, dcol + half * 32);
                TC_WAIT_LD();
#pragma unroll
                for (int c4 = 0; c4 < 8; c4++) {
                    float4 bb = *(const float4*)(sB2 + half * 32 + 4 * c4);
                    red4(op + half * 32 + 4 * c4,
                         __uint_as_float(d[4 * c4 + 0]) + bb.x,
                         __uint_as_float(d[4 * c4 + 1]) + bb.y,
                         __uint_as_float(d[4 * c4 + 2]) + bb.z,
                         __uint_as_float(d[4 * c4 + 3]) + bb.w);
                }
            }
        }

        // ---- stage next tile's eattr (A tile free: MMA2 completion waited) ----
        if (have_next) {
#pragma unroll
            for (int c = 0; c < 4; c++) {
                const float ev[8] = {pf[2 * c].x, pf[2 * c].y, pf[2 * c].z, pf[2 * c].w,
                                     pf[2 * c + 1].x, pf[2 * c + 1].y, pf[2 * c + 1].z,
                                     pf[2 * c + 1].w};
                uint32_t hw[4], lw[4];
#pragma unroll
                for (int p = 0; p < 4; p++) {
                    float f0 = ev[2 * p], f1 = ev[2 * p + 1];
                    __nv_bfloat16 h0 = __float2bfloat16(f0), h1 = __float2bfloat16(f1);
                    hw[p] = ((uint32_t)__bfloat16_as_ushort(h1) << 16) | __bfloat16_as_ushort(h0);
                    lw[p] = pack_bf16(f0 - __bfloat162float(h0), f1 - __bfloat162float(h1));
                }
                int so = SW(r * 128 + c * 16);
                *(uint4*)(aHi + so) = make_uint4(hw[0], hw[1], hw[2], hw[3]);
                *(uint4*)(aLo + so) = make_uint4(lw[0], lw[1], lw[2], lw[3]);
            }
            vi = nvi;
            vj = nvj;
        }
        FENCE_ASYNC();
        WG_SYNC(barid);
        tile = ntile;
    }

    __syncthreads();   // both WGs done before inval/dealloc
    if (t == 0) {
        MBAR_INVAL(sbase + MBAR_OFF);
        MBAR_INVAL(sbase + MBAR_OFF + 8);
    }
    __syncthreads();
    if (t < 32) TC_DEALLOC(tmem, 128);

#else
    // ======================= scalar fallback (R3, persistent loop) ==========
    float* sH = (float*)(smem + F_H_OFF);
    float* sW1c = (float*)(smem + F_W1C_OFF);
    float* sW2 = (float*)(smem + F_W2_OFF);
    int* sIi = (int*)(smem + F_II_OFF);
    int* sIj = (int*)(smem + F_IJ_OFF);
    float* sB1 = (float*)(smem + F_B_OFF);
    float* sB2 = sB1 + 64;
    float* sG = sB1 + 128;
    float* sBt = sB1 + 192;

    const int tr = t >> 3;
    const int tc = t & 7;

    {
        const float4* w1s = (const float4*)(W1 + 128 * 64);
#pragma unroll
        for (int i = 0; i < 2; i++) ((float4*)sW1c)[t + 256 * i] = w1s[t + 256 * i];
        const float4* w2s = (const float4*)W2;
#pragma unroll
        for (int i = 0; i < 4; i++) ((float4*)sW2)[t + 256 * i] = w2s[t + 256 * i];
        if (t < 64) { sB1[t] = b1[t]; sB2[t] = b2[t]; sG[t] = gamma_[t]; sBt[t] = beta_[t]; }
    }

    for (int tile = blockIdx.x; tile < N_TILES; tile += GRID_PERSIST) {
        const int Eb = tile * 256;
        __syncthreads();
        sIi[t] = eidx[Eb + t];
        sIj[t] = eidx[N_EDGES + Eb + t];
        {
            const float4* er = (const float4*)(eattr + (size_t)(Eb + t) * 32);
            float4 ev[8];
#pragma unroll
            for (int i = 0; i < 8; i++) ev[i] = __ldg(er + i);
            const float* evf = (const float*)ev;
            const int ecbase = t >> 3, off = t & 7;
#pragma unroll
            for (int k = 0; k < 32; k++)
                sH[k * 256 + ((ecbase ^ (k >> 3)) & 31) * 8 + off] = evf[k];
        }
        __syncthreads();

        unsigned long long acc[8][4];
        {
            float4 b1a = *(const float4*)(sB1 + tc * 8);
            float4 b1b = *(const float4*)(sB1 + tc * 8 + 4);
#pragma unroll
            for (int e = 0; e < 8; e++) {
                const int vi = sIi[tr * 8 + e];
                const int vj = sIj[tr * 8 + e];
                const float* Pr = g_P + (size_t)vi * 64 + tc * 8;
                const float* Qr = g_Q + (size_t)vj * 64 + tc * 8;
                float4 pa = *(const float4*)Pr;
                float4 pb = *(const float4*)(Pr + 4);
                float4 qa = *(const float4*)Qr;
                float4 qb = *(const float4*)(Qr + 4);
                acc[e][0] = pack2(pa.x + qa.x + b1a.x, pa.y + qa.y + b1a.y);
                acc[e][1] = pack2(pa.z + qa.z + b1a.z, pa.w + qa.w + b1a.w);
                acc[e][2] = pack2(pb.x + qb.x + b1b.x, pb.y + qb.y + b1b.y);
                acc[e][3] = pack2(pb.z + qb.z + b1b.z, pb.w + qb.w + b1b.w);
            }
        }
#pragma unroll
        for (int k = 0; k < 32; k++) {
            const float* arow = sH + k * 256 + ((tr ^ (k >> 3)) & 31) * 8;
            float4 a0 = *(const float4*)arow;
            float4 a1 = *(const float4*)(arow + 4);
            const ulonglong2 w0 = *(const ulonglong2*)(sW1c + k * 64 + tc * 8);
            const ulonglong2 w1 = *(const ulonglong2*)(sW1c + k * 64 + tc * 8 + 4);
            const float a[8] = {a0.x, a0.y, a0.z, a0.w, a1.x, a1.y, a1.z, a1.w};
#pragma unroll
            for (int e = 0; e < 8; e++) {
                unsigned long long ae = pack2(a[e], a[e]);
                acc[e][0] = ffma2(ae, w0.x, acc[e][0]);
                acc[e][1] = ffma2(ae, w0.y, acc[e][1]);
                acc[e][2] = ffma2(ae, w1.x, acc[e][2]);
                acc[e][3] = ffma2(ae, w1.y, acc[e][3]);
            }
        }

        float s[8], ss[8];
#pragma unroll
        for (int e = 0; e < 8; e++) {
            float h0, h1, h2, h3, h4, h5, h6, h7;
            unpack2(acc[e][0], h0, h1); unpack2(acc[e][1], h2, h3);
            unpack2(acc[e][2], h4, h5); unpack2(acc[e][3], h6, h7);
            s[e] = ((h0 + h1) + (h2 + h3)) + ((h4 + h5) + (h6 + h7));
            ss[e] = ((h0 * h0 + h1 * h1) + (h2 * h2 + h3 * h3)) +
                    ((h4 * h4 + h5 * h5) + (h6 * h6 + h7 * h7));
        }
#pragma unroll
        for (int m = 1; m < 8; m <<= 1) {
#pragma unroll
            for (int e = 0; e < 8; e++) {
                s[e] += __shfl_xor_sync(0xffffffffu, s[e], m);
                ss[e] += __shfl_xor_sync(0xffffffffu, ss[e], m);
            }
        }

        float4 ga = *(const float4*)(sG + tc * 8);
        float4 gb = *(const float4*)(sG + tc * 8 + 4);
        float4 ba = *(const float4*)(sBt + tc * 8);
        float4 bb = *(const float4*)(sBt + tc * 8 + 4);
        const float gg[8] = {ga.x, ga.y, ga.z, ga.w, gb.x, gb.y, gb.z, gb.w};
        const float bt[8] = {ba.x, ba.y, ba.z, ba.w, bb.x, bb.y, bb.z, bb.w};

        __syncthreads();

#pragma unroll
        for (int e = 0; e < 8; e++) {
            const float mu = s[e] * (1.0f / 64.0f);
            const float var = ss[e] * (1.0f / 64.0f) - mu * mu;
            const float rstd = rsqrtf(var + 1e-5f);
            float h[8];
            unpack2(acc[e][0], h[0], h[1]); unpack2(acc[e][1], h[2], h[3]);
            unpack2(acc[e][2], h[4], h[5]); unpack2(acc[e][3], h[6], h[7]);
#pragma unroll
            for (int c = 0; c < 8; c++) {
                float v = (h[c] - mu) * rstd * gg[c] + bt[c];
                h[c] = 0.5f * v * (1.0f + erff(v * 0.70710678118654752f));
            }
#pragma unroll
            for (int c = 0; c < 8; c++)
                sH[(tc * 8 + c) * 256 + ((tr ^ tc) & 31) * 8 + e] = h[c];
        }
        __syncthreads();

        {
            float4 b2a = *(const float4*)(sB2 + tc * 8);
            float4 b2b = *(const float4*)(sB2 + tc * 8 + 4);
#pragma unroll
            for (int e = 0; e < 8; e++) {
                acc[e][0] = pack2(b2a.x, b2a.y);
                acc[e][1] = pack2(b2a.z, b2a.w);
                acc[e][2] = pack2(b2b.x, b2b.y);
                acc[e][3] = pack2(b2b.z, b2b.w);
            }
        }
#pragma unroll
        for (int k = 0; k < 64; k++) {
            const float* arow = sH + k * 256 + ((tr ^ (k >> 3)) & 31) * 8;
            float4 a0 = *(const float4*)arow;
            float4 a1 = *(const float4*)(arow + 4);
            const ulonglong2 w0 = *(const ulonglong2*)(sW2 + k * 64 + tc * 8);
            const ulonglong2 w1 = *(const ulonglong2*)(sW2 + k * 64 + tc * 8 + 4);
            const float a[8] = {a0.x, a0.y, a0.z, a0.w, a1.x, a1.y, a1.z, a1.w};
#pragma unroll
            for (int e = 0; e < 8; e++) {
                unsigned long long ae = pack2(a[e], a[e]);
                acc[e][0] = ffma2(ae, w0.x, acc[e][0]);
                acc[e][1] = ffma2(ae, w0.y, acc[e][1]);
                acc[e][2] = ffma2(ae, w1.x, acc[e][2]);
                acc[e][3] = ffma2(ae, w1.y, acc[e][3]);
            }
        }

#pragma unroll
        for (int e = 0; e < 8; e++) {
            const int vj = sIj[tr * 8 + e];
            float* op = out + (size_t)vj * 64 + tc * 8;
            float m0, m1, m2, m3, m4, m5, m6, m7;
            unpack2(acc[e][0], m0, m1); unpack2(acc[e][1], m2, m3);
            unpack2(acc[e][2], m4, m5); unpack2(acc[e][3], m6, m7);
            red4(op, m0, m1, m2, m3);
            red4(op + 4, m4, m5, m6, m7);
        }
    }
#endif
}

extern "C" void kernel_launch(void* const* d_in, const int* in_sizes, int n_in,
                              void* d_out, int out_size) {
    const float* x = (const float*)d_in[0];
    const int* eidx = (const int*)d_in[1];
    const float* eattr = (const float*)d_in[2];
    const float* W1 = (const float*)d_in[3];
    const float* b1 = (const float*)d_in[4];
    const float* gamma_ = (const float*)d_in[5];
    const float* beta_ = (const float*)d_in[6];
    const float* W2 = (const float*)d_in[7];
    const float* b2 = (const float*)d_in[8];
    float* out = (float*)d_out;

    cudaFuncSetAttribute(edge_kernel, cudaFuncAttributeMaxDynamicSharedMemorySize, SMEM_TOTAL);

    zero_kernel<<<6250, 256>>>((float4*)out);
    split_weights_kernel<<<16, 256>>>(W1, W2);
    pq_kernel<<<dim3(1024, 2), 128>>>(x, W1);
    edge_kernel<<<GRID_PERSIST, 256, SMEM_TOTAL>>>(eidx, eattr, W1, b1, gamma_, beta_, W2, b2,
                                                   out);
}